// round 5
// baseline (speedup 1.0000x reference)
#include <cuda_runtime.h>
#include <math.h>

// Problem constants
#define BATCH  2048
#define HID    512
#define INDIM  128
#define OUTDIM 128
#define SEQ    128

// Step-kernel tiling (static smem: 16*64*8 + 4*16*68*4 = 25600 B)
#define BM 64
#define BN 64
#define BK 16
#define PADB 68
#define NT 256

// FC tiling
#define FBK 32
#define FPADN 132        // 128 + 4 pad

// FC batching: ring of RING steps, flushed every RING steps (32 MB scratch)
#define RING 16

typedef unsigned long long u64;

// Static device scratch (allocations are forbidden). ~40 MB total.
__device__ float g_hring[(size_t)RING * BATCH * HID];
__device__ float g_W4 [4 * HID * HID];               // combined weights  (steps >=1)
__device__ float g_W40[4 * HID * HID];               // combined weights  (step 0, x=0)
__device__ float g_b4 [4 * HID];
__device__ float g_b40[4 * HID];

// ---------------- packed f32x2 helpers (Blackwell FFMA2) ----------------
__device__ __forceinline__ u64 pack2(float lo, float hi) {
    u64 r;
    asm("mov.b64 %0, {%1, %2};" : "=l"(r) : "f"(lo), "f"(hi));
    return r;
}
__device__ __forceinline__ float2 unpack2(u64 v) {
    float2 f;
    asm("mov.b64 {%0, %1}, %2;" : "=f"(f.x), "=f"(f.y) : "l"(v));
    return f;
}
__device__ __forceinline__ u64 fma2(u64 a, u64 b, u64 c) {
    u64 d;
    asm("fma.rn.f32x2 %0, %1, %2, %3;" : "=l"(d) : "l"(a), "l"(b), "l"(c));
    return d;
}

__device__ __forceinline__ float gru_comb(float pr, float pz, float pin, float phn, float hp) {
    float r  = 1.0f / (1.0f + expf(-pr));
    float z  = 1.0f / (1.0f + expf(-pz));
    float nn = tanhf(pin + r * phn);
    return (1.0f - z) * nn + z * hp;
}

// ---------------- prep: fold FC into recurrent weights ----------------
// x_s = h_{s-1} @ fc_w^T + fc_b is linear in h_{s-1}, so the x-path folds:
// W4 strips (rows j = strip*512 + jl, cols k):
//   R : w_ih[jl]      @ fc_w + w_hh[jl]
//   Z : w_ih[512+jl]  @ fc_w + w_hh[512+jl]
//   IN: w_ih[1024+jl] @ fc_w
//   HN: w_hh[1024+jl]
// W40 (step 0, x=0): R/Z/HN = w_hh strips, IN = 0.
__global__ __launch_bounds__(NT)
void prep_w4(const float* __restrict__ w_ih, const float* __restrict__ w_hh,
             const float* __restrict__ fc_w)
{
    const int idx   = blockIdx.x * NT + threadIdx.x;   // 0 .. 4*512*512-1
    const int k     = idx & (HID - 1);
    const int j     = idx >> 9;
    const int strip = j >> 9;
    const int jl    = j & (HID - 1);

    float acc = 0.0f;
    if (strip < 3) {
        const int wrow = strip * HID + jl;
#pragma unroll 8
        for (int o = 0; o < INDIM; ++o)
            acc += w_ih[wrow * INDIM + o] * fc_w[o * HID + k];
    }
    float w4, w40;
    if (strip == 0)      { float w = w_hh[jl * HID + k];              w4 = acc + w; w40 = w; }
    else if (strip == 1) { float w = w_hh[(HID + jl) * HID + k];      w4 = acc + w; w40 = w; }
    else if (strip == 2) { w4 = acc; w40 = 0.0f; }
    else                 { float w = w_hh[(2 * HID + jl) * HID + k];  w4 = w;       w40 = w; }
    g_W4[idx]  = w4;
    g_W40[idx] = w40;
}

__global__ __launch_bounds__(NT)
void prep_b4(const float* __restrict__ w_ih, const float* __restrict__ b_ih,
             const float* __restrict__ b_hh, const float* __restrict__ fc_b)
{
    const int j = blockIdx.x * NT + threadIdx.x;       // 0..2047
    const int strip = j >> 9;
    const int jl    = j & (HID - 1);

    float acc = 0.0f;
    if (strip < 3) {
        const int wrow = strip * HID + jl;
#pragma unroll 8
        for (int o = 0; o < INDIM; ++o)
            acc += w_ih[wrow * INDIM + o] * fc_b[o];
    }
    float b, b0;
    if (strip == 0)      { b0 = b_ih[jl] + b_hh[jl];                     b = acc + b0; }
    else if (strip == 1) { b0 = b_ih[HID + jl] + b_hh[HID + jl];         b = acc + b0; }
    else if (strip == 2) { b0 = b_ih[2 * HID + jl];                      b = acc + b0; }
    else                 { b0 = b_hh[2 * HID + jl];                      b = b0; }
    g_b4[j]  = b;
    g_b40[j] = b0;
}

// ---------------- per-step kernel: h_s = GRU(h_{s-1}) via combined weights ----------------
// grid (BATCH/BM, HID/BN) = (32, 8); each block: 64 batch rows x 64 h'-cols,
// accumulating 4 strips (R,Z,IN,HN) over K=512. Static smem only.
__global__ __launch_bounds__(NT)
void step_kernel(int s, const float* __restrict__ hidden)
{
    __shared__ __align__(16) u64   As2[BK * BM];        // duplicated f32x2, 8 KB
    __shared__ __align__(16) float Bs[4 * BK * PADB];   // 4 strips, 17.4 KB

    const float* h_prev = (s == 0) ? hidden
                        : (g_hring + (size_t)((s - 1) & (RING - 1)) * BATCH * HID);
    float*       h_out  = g_hring + (size_t)(s & (RING - 1)) * BATCH * HID;
    const float* W      = (s == 0) ? g_W40 : g_W4;
    const float* bias   = (s == 0) ? g_b40 : g_b4;

    const int m0 = blockIdx.x * BM;
    const int c0 = blockIdx.y * BN;
    const int t  = threadIdx.x;
    const int tx = t & 15;           // 4 cols each
    const int ty = t >> 4;           // 4 rows each
    const int lrow = t >> 2;         // 0..63  loader row
    const int lc4  = (t & 3) << 2;   // 0,4,8,12 loader col group (4 floats)

    u64 acc[4][4][2];
#pragma unroll
    for (int g = 0; g < 4; ++g)
#pragma unroll
        for (int i = 0; i < 4; ++i)
            acc[g][i][0] = acc[g][i][1] = 0ull;

    for (int kb = 0; kb < HID; kb += BK) {
        // load A (h_prev tile), store duplicated pairs
        {
            const float4 a0 = *reinterpret_cast<const float4*>(
                &h_prev[(size_t)(m0 + lrow) * HID + kb + lc4]);
            As2[(lc4 + 0) * BM + lrow] = pack2(a0.x, a0.x);
            As2[(lc4 + 1) * BM + lrow] = pack2(a0.y, a0.y);
            As2[(lc4 + 2) * BM + lrow] = pack2(a0.z, a0.z);
            As2[(lc4 + 3) * BM + lrow] = pack2(a0.w, a0.w);
        }
        // load 4 W strips (transposed into [kk][row])
#pragma unroll
        for (int g = 0; g < 4; ++g) {
            const float4 b0 = *reinterpret_cast<const float4*>(
                &W[(size_t)(g * HID + c0 + lrow) * HID + kb + lc4]);
            float* dst = Bs + (size_t)g * BK * PADB;
            dst[(lc4 + 0) * PADB + lrow] = b0.x;
            dst[(lc4 + 1) * PADB + lrow] = b0.y;
            dst[(lc4 + 2) * PADB + lrow] = b0.z;
            dst[(lc4 + 3) * PADB + lrow] = b0.w;
        }
        __syncthreads();

#pragma unroll
        for (int kk = 0; kk < BK; ++kk) {
            const ulonglong2 a01 = *reinterpret_cast<const ulonglong2*>(
                &As2[kk * BM + (ty << 2)]);
            const ulonglong2 a23 = *reinterpret_cast<const ulonglong2*>(
                &As2[kk * BM + (ty << 2) + 2]);
            const u64 av0 = a01.x, av1 = a01.y, av2 = a23.x, av3 = a23.y;
#pragma unroll
            for (int g = 0; g < 4; ++g) {
                const ulonglong2 bv = *reinterpret_cast<const ulonglong2*>(
                    &Bs[(size_t)(g * BK + kk) * PADB + (tx << 2)]);
                acc[g][0][0] = fma2(av0, bv.x, acc[g][0][0]);
                acc[g][0][1] = fma2(av0, bv.y, acc[g][0][1]);
                acc[g][1][0] = fma2(av1, bv.x, acc[g][1][0]);
                acc[g][1][1] = fma2(av1, bv.y, acc[g][1][1]);
                acc[g][2][0] = fma2(av2, bv.x, acc[g][2][0]);
                acc[g][2][1] = fma2(av2, bv.y, acc[g][2][1]);
                acc[g][3][0] = fma2(av3, bv.x, acc[g][3][0]);
                acc[g][3][1] = fma2(av3, bv.y, acc[g][3][1]);
            }
        }
        __syncthreads();
    }

    // ---- epilogue: gates + blend + write h_s ----
    const int col = c0 + (tx << 2);
    const float4 bR = *reinterpret_cast<const float4*>(&bias[col]);
    const float4 bZ = *reinterpret_cast<const float4*>(&bias[HID + col]);
    const float4 bI = *reinterpret_cast<const float4*>(&bias[2 * HID + col]);
    const float4 bH = *reinterpret_cast<const float4*>(&bias[3 * HID + col]);

#pragma unroll
    for (int i = 0; i < 4; ++i) {
        const size_t row = m0 + (ty << 2) + i;
        const float4 hp = *reinterpret_cast<const float4*>(&h_prev[row * HID + col]);
        const float2 r0 = unpack2(acc[0][i][0]), r1 = unpack2(acc[0][i][1]);
        const float2 z0 = unpack2(acc[1][i][0]), z1 = unpack2(acc[1][i][1]);
        const float2 n0 = unpack2(acc[2][i][0]), n1 = unpack2(acc[2][i][1]);
        const float2 g0 = unpack2(acc[3][i][0]), g1 = unpack2(acc[3][i][1]);
        float4 o;
        o.x = gru_comb(r0.x + bR.x, z0.x + bZ.x, n0.x + bI.x, g0.x + bH.x, hp.x);
        o.y = gru_comb(r0.y + bR.y, z0.y + bZ.y, n0.y + bI.y, g0.y + bH.y, hp.y);
        o.z = gru_comb(r1.x + bR.z, z1.x + bZ.z, n1.x + bI.z, g1.x + bH.z, hp.z);
        o.w = gru_comb(r1.y + bR.w, z1.y + bZ.w, n1.y + bI.w, g1.y + bH.w, hp.w);
        *reinterpret_cast<float4*>(&h_out[row * HID + col]) = o;
    }
}

// ---------------- batched FC: y over RING steps = ring @ fc_w^T + fc_b ----------------
// Ring slots 0..RING-1 hold steps s0..s0+RING-1 (contiguous, in order).
// Row r -> (s_local = r>>11, b = r&2047); written to out[b][SEQ-1-(s0+s_local)][:].
__global__ __launch_bounds__(NT)
void fc_batch(int s0, const float* __restrict__ fc_w, const float* __restrict__ fc_b,
              float* __restrict__ out)
{
    __shared__ __align__(16) u64   As2[FBK * BM];       // duplicated pairs, 16 KB
    __shared__ __align__(16) float Bs[FBK * FPADN];     // 16.9 KB

    const int r0 = blockIdx.x * BM;
    const int t  = threadIdx.x;
    const int tx = t & 15;           // 8 cols each
    const int ty = t >> 4;           // 4 rows each
    const int arow = t >> 2;         // A loader: 0..63
    const int acg  = (t & 3) << 3;   // 8 floats
    const int brow = t >> 1;         // B loader: 0..127
    const int bcg  = (t & 1) << 4;   // 16 floats

    u64 acc[4][4];
#pragma unroll
    for (int i = 0; i < 4; ++i)
#pragma unroll
        for (int p = 0; p < 4; ++p) acc[i][p] = 0ull;

    for (int kb = 0; kb < HID; kb += FBK) {
        {
            const float4* ap = reinterpret_cast<const float4*>(
                &g_hring[(size_t)(r0 + arow) * HID + kb + acg]);
            const float4 a0 = ap[0], a1 = ap[1];
            As2[(acg + 0) * BM + arow] = pack2(a0.x, a0.x);
            As2[(acg + 1) * BM + arow] = pack2(a0.y, a0.y);
            As2[(acg + 2) * BM + arow] = pack2(a0.z, a0.z);
            As2[(acg + 3) * BM + arow] = pack2(a0.w, a0.w);
            As2[(acg + 4) * BM + arow] = pack2(a1.x, a1.x);
            As2[(acg + 5) * BM + arow] = pack2(a1.y, a1.y);
            As2[(acg + 6) * BM + arow] = pack2(a1.z, a1.z);
            As2[(acg + 7) * BM + arow] = pack2(a1.w, a1.w);
        }
        {
            const float4* bp = reinterpret_cast<const float4*>(
                &fc_w[(size_t)brow * HID + kb + bcg]);
            const float4 b0 = bp[0], b1 = bp[1], b2 = bp[2], b3 = bp[3];
            Bs[(bcg +  0) * FPADN + brow] = b0.x;
            Bs[(bcg +  1) * FPADN + brow] = b0.y;
            Bs[(bcg +  2) * FPADN + brow] = b0.z;
            Bs[(bcg +  3) * FPADN + brow] = b0.w;
            Bs[(bcg +  4) * FPADN + brow] = b1.x;
            Bs[(bcg +  5) * FPADN + brow] = b1.y;
            Bs[(bcg +  6) * FPADN + brow] = b1.z;
            Bs[(bcg +  7) * FPADN + brow] = b1.w;
            Bs[(bcg +  8) * FPADN + brow] = b2.x;
            Bs[(bcg +  9) * FPADN + brow] = b2.y;
            Bs[(bcg + 10) * FPADN + brow] = b2.z;
            Bs[(bcg + 11) * FPADN + brow] = b2.w;
            Bs[(bcg + 12) * FPADN + brow] = b3.x;
            Bs[(bcg + 13) * FPADN + brow] = b3.y;
            Bs[(bcg + 14) * FPADN + brow] = b3.z;
            Bs[(bcg + 15) * FPADN + brow] = b3.w;
        }
        __syncthreads();

#pragma unroll
        for (int kk = 0; kk < FBK; ++kk) {
            const ulonglong2 a01 = *reinterpret_cast<const ulonglong2*>(
                &As2[kk * BM + (ty << 2)]);
            const ulonglong2 a23 = *reinterpret_cast<const ulonglong2*>(
                &As2[kk * BM + (ty << 2) + 2]);
            const ulonglong2 bv0 = *reinterpret_cast<const ulonglong2*>(
                &Bs[(size_t)kk * FPADN + (tx << 3)]);
            const ulonglong2 bv1 = *reinterpret_cast<const ulonglong2*>(
                &Bs[(size_t)kk * FPADN + (tx << 3) + 4]);
            acc[0][0] = fma2(a01.x, bv0.x, acc[0][0]);
            acc[0][1] = fma2(a01.x, bv0.y, acc[0][1]);
            acc[0][2] = fma2(a01.x, bv1.x, acc[0][2]);
            acc[0][3] = fma2(a01.x, bv1.y, acc[0][3]);
            acc[1][0] = fma2(a01.y, bv0.x, acc[1][0]);
            acc[1][1] = fma2(a01.y, bv0.y, acc[1][1]);
            acc[1][2] = fma2(a01.y, bv1.x, acc[1][2]);
            acc[1][3] = fma2(a01.y, bv1.y, acc[1][3]);
            acc[2][0] = fma2(a23.x, bv0.x, acc[2][0]);
            acc[2][1] = fma2(a23.x, bv0.y, acc[2][1]);
            acc[2][2] = fma2(a23.x, bv1.x, acc[2][2]);
            acc[2][3] = fma2(a23.x, bv1.y, acc[2][3]);
            acc[3][0] = fma2(a23.y, bv0.x, acc[3][0]);
            acc[3][1] = fma2(a23.y, bv0.y, acc[3][1]);
            acc[3][2] = fma2(a23.y, bv1.x, acc[3][2]);
            acc[3][3] = fma2(a23.y, bv1.y, acc[3][3]);
        }
        __syncthreads();
    }

    const int col = tx << 3;
    const float4 fb0 = *reinterpret_cast<const float4*>(&fc_b[col]);
    const float4 fb1 = *reinterpret_cast<const float4*>(&fc_b[col + 4]);

#pragma unroll
    for (int i = 0; i < 4; ++i) {
        const int r = r0 + (ty << 2) + i;
        const int s = s0 + (r >> 11);    // 2048 rows per step
        const int b = r & (BATCH - 1);
        float* dst = out + (size_t)b * SEQ * OUTDIM + (size_t)(SEQ - 1 - s) * OUTDIM + col;
        const float2 p0 = unpack2(acc[i][0]);
        const float2 p1 = unpack2(acc[i][1]);
        const float2 p2 = unpack2(acc[i][2]);
        const float2 p3 = unpack2(acc[i][3]);
        float4 o0, o1;
        o0.x = p0.x + fb0.x; o0.y = p0.y + fb0.y; o0.z = p1.x + fb0.z; o0.w = p1.y + fb0.w;
        o1.x = p2.x + fb1.x; o1.y = p2.y + fb1.y; o1.z = p3.x + fb1.z; o1.w = p3.y + fb1.w;
        *reinterpret_cast<float4*>(dst)     = o0;
        *reinterpret_cast<float4*>(dst + 4) = o1;
    }
}

// ---------------- launch (launches only; deterministic) ----------------
// inputs: hidden, w_ih, w_hh, b_ih, b_hh, fc_w, fc_b, seq_len
extern "C" void kernel_launch(void* const* d_in, const int* in_sizes, int n_in,
                              void* d_out, int out_size)
{
    const float* hidden = (const float*)d_in[0];
    const float* w_ih   = (const float*)d_in[1];
    const float* w_hh   = (const float*)d_in[2];
    const float* b_ih   = (const float*)d_in[3];
    const float* b_hh   = (const float*)d_in[4];
    const float* fc_w   = (const float*)d_in[5];
    const float* fc_b   = (const float*)d_in[6];
    float* out = (float*)d_out;

    prep_w4<<<4 * HID * HID / NT, NT>>>(w_ih, w_hh, fc_w);
    prep_b4<<<4 * HID / NT, NT>>>(w_ih, b_ih, b_hh, fc_b);

    const dim3 gridS(BATCH / BM, HID / BN);          // 32 x 8 = 256 blocks
    for (int s = 0; s < SEQ; ++s) {
        step_kernel<<<gridS, NT>>>(s, hidden);
        if ((s & (RING - 1)) == RING - 1) {
            // flush steps s-RING+1 .. s  (ring slots 0..RING-1, in order)
            fc_batch<<<RING * BATCH / BM, NT>>>(s - RING + 1, fc_w, fc_b, out);
        }
    }
}

// round 6
// speedup vs baseline: 1.1083x; 1.1083x over previous
#include <cuda_runtime.h>
#include <math.h>

// Problem constants
#define BATCH  2048
#define HID    512
#define INDIM  128
#define OUTDIM 128
#define SEQ    128

// Step-kernel tiling: block = 128 rows x 32 cols x 4 gates, 256 threads.
// Thread tile: 8 rows x 2 cols (1 f32x2) x 4 gates = 32 FFMA2 per kk.
#define SBM 128
#define SBN 32
#define BK  16
#define AST 132           // A smem row stride (floats): 16B-aligned, conflict-free stores
#define BST 34            // B smem kk stride (floats): 8B-aligned, conflict-free
#define BSEG (BK * BST)   // per-gate B segment
#define NT  256

// FC tiling
#define FBM 64
#define FBK 32
#define FPADN 132

// FC batching: ring of RING steps, flushed every RING steps (32 MB scratch)
#define RING 16

typedef unsigned long long u64;

// Static device scratch (~40 MB; allocations are forbidden).
__device__ float g_hring[(size_t)RING * BATCH * HID];
__device__ float g_W4 [4 * HID * HID];               // combined weights  (steps >=1)
__device__ float g_W40[4 * HID * HID];               // combined weights  (step 0, x=0)
__device__ float g_b4 [4 * HID];
__device__ float g_b40[4 * HID];

// ---------------- packed f32x2 helpers (Blackwell FFMA2) ----------------
__device__ __forceinline__ u64 pack2(float lo, float hi) {
    u64 r;
    asm("mov.b64 %0, {%1, %2};" : "=l"(r) : "f"(lo), "f"(hi));
    return r;
}
__device__ __forceinline__ float2 unpack2(u64 v) {
    float2 f;
    asm("mov.b64 {%0, %1}, %2;" : "=f"(f.x), "=f"(f.y) : "l"(v));
    return f;
}
__device__ __forceinline__ u64 fma2(u64 a, u64 b, u64 c) {
    u64 d;
    asm("fma.rn.f32x2 %0, %1, %2, %3;" : "=l"(d) : "l"(a), "l"(b), "l"(c));
    return d;
}

__device__ __forceinline__ float gru_comb(float pr, float pz, float pin, float phn, float hp) {
    float r  = 1.0f / (1.0f + expf(-pr));
    float z  = 1.0f / (1.0f + expf(-pz));
    float nn = tanhf(pin + r * phn);
    return (1.0f - z) * nn + z * hp;
}

// ---------------- prep: fold FC into recurrent weights ----------------
// x_s = h_{s-1} @ fc_w^T + fc_b is linear in h_{s-1}, so the x-path folds:
// W4 strips (rows j = strip*512 + jl, cols k):
//   R : w_ih[jl]      @ fc_w + w_hh[jl]
//   Z : w_ih[512+jl]  @ fc_w + w_hh[512+jl]
//   IN: w_ih[1024+jl] @ fc_w
//   HN: w_hh[1024+jl]
// W40 (step 0, x=0): R/Z/HN = w_hh strips, IN = 0.
__global__ __launch_bounds__(NT)
void prep_w4(const float* __restrict__ w_ih, const float* __restrict__ w_hh,
             const float* __restrict__ fc_w)
{
    const int idx   = blockIdx.x * NT + threadIdx.x;   // 0 .. 4*512*512-1
    const int k     = idx & (HID - 1);
    const int j     = idx >> 9;
    const int strip = j >> 9;
    const int jl    = j & (HID - 1);

    float acc = 0.0f;
    if (strip < 3) {
        const int wrow = strip * HID + jl;
#pragma unroll 8
        for (int o = 0; o < INDIM; ++o)
            acc += w_ih[wrow * INDIM + o] * fc_w[o * HID + k];
    }
    float w4, w40;
    if (strip == 0)      { float w = w_hh[jl * HID + k];              w4 = acc + w; w40 = w; }
    else if (strip == 1) { float w = w_hh[(HID + jl) * HID + k];      w4 = acc + w; w40 = w; }
    else if (strip == 2) { w4 = acc; w40 = 0.0f; }
    else                 { float w = w_hh[(2 * HID + jl) * HID + k];  w4 = w;       w40 = w; }
    g_W4[idx]  = w4;
    g_W40[idx] = w40;
}

__global__ __launch_bounds__(NT)
void prep_b4(const float* __restrict__ w_ih, const float* __restrict__ b_ih,
             const float* __restrict__ b_hh, const float* __restrict__ fc_b)
{
    const int j = blockIdx.x * NT + threadIdx.x;       // 0..2047
    const int strip = j >> 9;
    const int jl    = j & (HID - 1);

    float acc = 0.0f;
    if (strip < 3) {
        const int wrow = strip * HID + jl;
#pragma unroll 8
        for (int o = 0; o < INDIM; ++o)
            acc += w_ih[wrow * INDIM + o] * fc_b[o];
    }
    float b, b0;
    if (strip == 0)      { b0 = b_ih[jl] + b_hh[jl];                     b = acc + b0; }
    else if (strip == 1) { b0 = b_ih[HID + jl] + b_hh[HID + jl];         b = acc + b0; }
    else if (strip == 2) { b0 = b_ih[2 * HID + jl];                      b = acc + b0; }
    else                 { b0 = b_hh[2 * HID + jl];                      b = b0; }
    g_b4[j]  = b;
    g_b40[j] = b0;
}

// ---------------- per-step kernel: h_s = GRU(h_{s-1}) via combined weights ----------------
// grid (BATCH/SBM, HID/SBN) = (16, 16) = 256 blocks; 2 blocks/SM (reg-capped 128).
// Per thread: 8 rows x 2 cols x 4 gates; A plain in smem (dup in regs), B plain f32x2 pairs.
__global__ __launch_bounds__(NT, 2)
void step_kernel(int s, const float* __restrict__ hidden)
{
    __shared__ __align__(16) float As[BK * AST];        // [kk][row], 8.4 KB
    __shared__ __align__(16) float Bs[4 * BSEG];        // [g][kk][col], 8.7 KB

    const float* h_prev = (s == 0) ? hidden
                        : (g_hring + (size_t)((s - 1) & (RING - 1)) * BATCH * HID);
    float*       h_out  = g_hring + (size_t)(s & (RING - 1)) * BATCH * HID;
    const float* W      = (s == 0) ? g_W40 : g_W4;
    const float* bias   = (s == 0) ? g_b40 : g_b4;

    const int m0 = blockIdx.x * SBM;
    const int c0 = blockIdx.y * SBN;
    const int t  = threadIdx.x;
    const int tx = t & 15;           // col-pair index (2 cols)
    const int ty = t >> 4;           // row group (8 rows)

    // A loader: row = t&127, kseg = t>>7 selects 8 of 16 k-cols
    const int alrow = t & 127;
    const int akseg = (t >> 7) << 3;
    // B loader: g = t>>6, u = t&63: col = u&31, kseg = (u>>5)*8
    const int bg    = t >> 6;
    const int bcol  = t & 31;
    const int bkseg = ((t >> 5) & 1) << 3;

    u64 acc[4][8];
#pragma unroll
    for (int g = 0; g < 4; ++g)
#pragma unroll
        for (int i = 0; i < 8; ++i)
            acc[g][i] = 0ull;

    for (int kb = 0; kb < HID; kb += BK) {
        // ---- load A tile (SBM x BK) transposed -> As[kk][row] ----
        {
            const float4* ap = reinterpret_cast<const float4*>(
                &h_prev[(size_t)(m0 + alrow) * HID + kb + akseg]);
            const float4 a0 = ap[0], a1 = ap[1];
            As[(akseg + 0) * AST + alrow] = a0.x;
            As[(akseg + 1) * AST + alrow] = a0.y;
            As[(akseg + 2) * AST + alrow] = a0.z;
            As[(akseg + 3) * AST + alrow] = a0.w;
            As[(akseg + 4) * AST + alrow] = a1.x;
            As[(akseg + 5) * AST + alrow] = a1.y;
            As[(akseg + 6) * AST + alrow] = a1.z;
            As[(akseg + 7) * AST + alrow] = a1.w;
        }
        // ---- load B tile: 4 gates x (BK x SBN) transposed -> Bs[g][kk][col] ----
        {
            const float4* bp = reinterpret_cast<const float4*>(
                &W[(size_t)(bg * HID + c0 + bcol) * HID + kb + bkseg]);
            const float4 b0 = bp[0], b1 = bp[1];
            float* dst = Bs + bg * BSEG + bcol;
            dst[(bkseg + 0) * BST] = b0.x;
            dst[(bkseg + 1) * BST] = b0.y;
            dst[(bkseg + 2) * BST] = b0.z;
            dst[(bkseg + 3) * BST] = b0.w;
            dst[(bkseg + 4) * BST] = b1.x;
            dst[(bkseg + 5) * BST] = b1.y;
            dst[(bkseg + 6) * BST] = b1.z;
            dst[(bkseg + 7) * BST] = b1.w;
        }
        __syncthreads();

#pragma unroll
        for (int kk = 0; kk < BK; ++kk) {
            const float4 a0 = *reinterpret_cast<const float4*>(&As[kk * AST + (ty << 3)]);
            const float4 a1 = *reinterpret_cast<const float4*>(&As[kk * AST + (ty << 3) + 4]);
            u64 ad[8];
            ad[0] = pack2(a0.x, a0.x);
            ad[1] = pack2(a0.y, a0.y);
            ad[2] = pack2(a0.z, a0.z);
            ad[3] = pack2(a0.w, a0.w);
            ad[4] = pack2(a1.x, a1.x);
            ad[5] = pack2(a1.y, a1.y);
            ad[6] = pack2(a1.z, a1.z);
            ad[7] = pack2(a1.w, a1.w);
            const u64 bv0 = *reinterpret_cast<const u64*>(&Bs[0 * BSEG + kk * BST + (tx << 1)]);
            const u64 bv1 = *reinterpret_cast<const u64*>(&Bs[1 * BSEG + kk * BST + (tx << 1)]);
            const u64 bv2 = *reinterpret_cast<const u64*>(&Bs[2 * BSEG + kk * BST + (tx << 1)]);
            const u64 bv3 = *reinterpret_cast<const u64*>(&Bs[3 * BSEG + kk * BST + (tx << 1)]);
#pragma unroll
            for (int i = 0; i < 8; ++i) {
                acc[0][i] = fma2(ad[i], bv0, acc[0][i]);
                acc[1][i] = fma2(ad[i], bv1, acc[1][i]);
                acc[2][i] = fma2(ad[i], bv2, acc[2][i]);
                acc[3][i] = fma2(ad[i], bv3, acc[3][i]);
            }
        }
        __syncthreads();
    }

    // ---- epilogue: gates + blend + write h_s (8 rows x 2 cols per thread) ----
    const int col = c0 + (tx << 1);
    const float2 bR = *reinterpret_cast<const float2*>(&bias[col]);
    const float2 bZ = *reinterpret_cast<const float2*>(&bias[HID + col]);
    const float2 bI = *reinterpret_cast<const float2*>(&bias[2 * HID + col]);
    const float2 bH = *reinterpret_cast<const float2*>(&bias[3 * HID + col]);

#pragma unroll
    for (int i = 0; i < 8; ++i) {
        const size_t row = m0 + (ty << 3) + i;
        const float2 hp = *reinterpret_cast<const float2*>(&h_prev[row * HID + col]);
        const float2 rr = unpack2(acc[0][i]);
        const float2 zz = unpack2(acc[1][i]);
        const float2 ii = unpack2(acc[2][i]);
        const float2 gg = unpack2(acc[3][i]);
        float2 o;
        o.x = gru_comb(rr.x + bR.x, zz.x + bZ.x, ii.x + bI.x, gg.x + bH.x, hp.x);
        o.y = gru_comb(rr.y + bR.y, zz.y + bZ.y, ii.y + bI.y, gg.y + bH.y, hp.y);
        *reinterpret_cast<float2*>(&h_out[row * HID + col]) = o;
    }
}

// ---------------- batched FC: y over RING steps = ring @ fc_w^T + fc_b ----------------
// Ring slots 0..RING-1 hold steps s0..s0+RING-1 (contiguous, in order).
// Row r -> (s_local = r>>11, b = r&2047); written to out[b][SEQ-1-(s0+s_local)][:].
__global__ __launch_bounds__(NT)
void fc_batch(int s0, const float* __restrict__ fc_w, const float* __restrict__ fc_b,
              float* __restrict__ out)
{
    __shared__ __align__(16) u64   As2[FBK * FBM];      // duplicated pairs, 16 KB
    __shared__ __align__(16) float Bs[FBK * FPADN];     // 16.9 KB

    const int r0 = blockIdx.x * FBM;
    const int t  = threadIdx.x;
    const int tx = t & 15;           // 8 cols each
    const int ty = t >> 4;           // 4 rows each
    const int arow = t >> 2;         // A loader: 0..63
    const int acg  = (t & 3) << 3;   // 8 floats
    const int brow = t >> 1;         // B loader: 0..127
    const int bcg  = (t & 1) << 4;   // 16 floats

    u64 acc[4][4];
#pragma unroll
    for (int i = 0; i < 4; ++i)
#pragma unroll
        for (int p = 0; p < 4; ++p) acc[i][p] = 0ull;

    for (int kb = 0; kb < HID; kb += FBK) {
        {
            const float4* ap = reinterpret_cast<const float4*>(
                &g_hring[(size_t)(r0 + arow) * HID + kb + acg]);
            const float4 a0 = ap[0], a1 = ap[1];
            As2[(acg + 0) * FBM + arow] = pack2(a0.x, a0.x);
            As2[(acg + 1) * FBM + arow] = pack2(a0.y, a0.y);
            As2[(acg + 2) * FBM + arow] = pack2(a0.z, a0.z);
            As2[(acg + 3) * FBM + arow] = pack2(a0.w, a0.w);
            As2[(acg + 4) * FBM + arow] = pack2(a1.x, a1.x);
            As2[(acg + 5) * FBM + arow] = pack2(a1.y, a1.y);
            As2[(acg + 6) * FBM + arow] = pack2(a1.z, a1.z);
            As2[(acg + 7) * FBM + arow] = pack2(a1.w, a1.w);
        }
        {
            const float4* bp = reinterpret_cast<const float4*>(
                &fc_w[(size_t)brow * HID + kb + bcg]);
            const float4 b0 = bp[0], b1 = bp[1], b2 = bp[2], b3 = bp[3];
            Bs[(bcg +  0) * FPADN + brow] = b0.x;
            Bs[(bcg +  1) * FPADN + brow] = b0.y;
            Bs[(bcg +  2) * FPADN + brow] = b0.z;
            Bs[(bcg +  3) * FPADN + brow] = b0.w;
            Bs[(bcg +  4) * FPADN + brow] = b1.x;
            Bs[(bcg +  5) * FPADN + brow] = b1.y;
            Bs[(bcg +  6) * FPADN + brow] = b1.z;
            Bs[(bcg +  7) * FPADN + brow] = b1.w;
            Bs[(bcg +  8) * FPADN + brow] = b2.x;
            Bs[(bcg +  9) * FPADN + brow] = b2.y;
            Bs[(bcg + 10) * FPADN + brow] = b2.z;
            Bs[(bcg + 11) * FPADN + brow] = b2.w;
            Bs[(bcg + 12) * FPADN + brow] = b3.x;
            Bs[(bcg + 13) * FPADN + brow] = b3.y;
            Bs[(bcg + 14) * FPADN + brow] = b3.z;
            Bs[(bcg + 15) * FPADN + brow] = b3.w;
        }
        __syncthreads();

#pragma unroll
        for (int kk = 0; kk < FBK; ++kk) {
            const ulonglong2 a01 = *reinterpret_cast<const ulonglong2*>(
                &As2[kk * FBM + (ty << 2)]);
            const ulonglong2 a23 = *reinterpret_cast<const ulonglong2*>(
                &As2[kk * FBM + (ty << 2) + 2]);
            const ulonglong2 bv0 = *reinterpret_cast<const ulonglong2*>(
                &Bs[(size_t)kk * FPADN + (tx << 3)]);
            const ulonglong2 bv1 = *reinterpret_cast<const ulonglong2*>(
                &Bs[(size_t)kk * FPADN + (tx << 3) + 4]);
            acc[0][0] = fma2(a01.x, bv0.x, acc[0][0]);
            acc[0][1] = fma2(a01.x, bv0.y, acc[0][1]);
            acc[0][2] = fma2(a01.x, bv1.x, acc[0][2]);
            acc[0][3] = fma2(a01.x, bv1.y, acc[0][3]);
            acc[1][0] = fma2(a01.y, bv0.x, acc[1][0]);
            acc[1][1] = fma2(a01.y, bv0.y, acc[1][1]);
            acc[1][2] = fma2(a01.y, bv1.x, acc[1][2]);
            acc[1][3] = fma2(a01.y, bv1.y, acc[1][3]);
            acc[2][0] = fma2(a23.x, bv0.x, acc[2][0]);
            acc[2][1] = fma2(a23.x, bv0.y, acc[2][1]);
            acc[2][2] = fma2(a23.x, bv1.x, acc[2][2]);
            acc[2][3] = fma2(a23.x, bv1.y, acc[2][3]);
            acc[3][0] = fma2(a23.y, bv0.x, acc[3][0]);
            acc[3][1] = fma2(a23.y, bv0.y, acc[3][1]);
            acc[3][2] = fma2(a23.y, bv1.x, acc[3][2]);
            acc[3][3] = fma2(a23.y, bv1.y, acc[3][3]);
        }
        __syncthreads();
    }

    const int col = tx << 3;
    const float4 fb0 = *reinterpret_cast<const float4*>(&fc_b[col]);
    const float4 fb1 = *reinterpret_cast<const float4*>(&fc_b[col + 4]);

#pragma unroll
    for (int i = 0; i < 4; ++i) {
        const int r = r0 + (ty << 2) + i;
        const int s = s0 + (r >> 11);    // 2048 rows per step
        const int b = r & (BATCH - 1);
        float* dst = out + (size_t)b * SEQ * OUTDIM + (size_t)(SEQ - 1 - s) * OUTDIM + col;
        const float2 p0 = unpack2(acc[i][0]);
        const float2 p1 = unpack2(acc[i][1]);
        const float2 p2 = unpack2(acc[i][2]);
        const float2 p3 = unpack2(acc[i][3]);
        float4 o0, o1;
        o0.x = p0.x + fb0.x; o0.y = p0.y + fb0.y; o0.z = p1.x + fb0.z; o0.w = p1.y + fb0.w;
        o1.x = p2.x + fb1.x; o1.y = p2.y + fb1.y; o1.z = p3.x + fb1.z; o1.w = p3.y + fb1.w;
        *reinterpret_cast<float4*>(dst)     = o0;
        *reinterpret_cast<float4*>(dst + 4) = o1;
    }
}

// ---------------- launch (launches only; deterministic) ----------------
// inputs: hidden, w_ih, w_hh, b_ih, b_hh, fc_w, fc_b, seq_len
extern "C" void kernel_launch(void* const* d_in, const int* in_sizes, int n_in,
                              void* d_out, int out_size)
{
    const float* hidden = (const float*)d_in[0];
    const float* w_ih   = (const float*)d_in[1];
    const float* w_hh   = (const float*)d_in[2];
    const float* b_ih   = (const float*)d_in[3];
    const float* b_hh   = (const float*)d_in[4];
    const float* fc_w   = (const float*)d_in[5];
    const float* fc_b   = (const float*)d_in[6];
    float* out = (float*)d_out;

    prep_w4<<<4 * HID * HID / NT, NT>>>(w_ih, w_hh, fc_w);
    prep_b4<<<4 * HID / NT, NT>>>(w_ih, b_ih, b_hh, fc_b);

    const dim3 gridS(BATCH / SBM, HID / SBN);        // 16 x 16 = 256 blocks
    for (int s = 0; s < SEQ; ++s) {
        step_kernel<<<gridS, NT>>>(s, hidden);
        if ((s & (RING - 1)) == RING - 1) {
            // flush steps s-RING+1 .. s  (ring slots 0..RING-1, in order)
            fc_batch<<<RING * BATCH / FBM, NT>>>(s - RING + 1, fc_w, fc_b, out);
        }
    }
}

// round 9
// speedup vs baseline: 2.2251x; 2.0077x over previous
#include <cuda_runtime.h>
#include <cuda_bf16.h>
#include <math.h>
#include <stdint.h>

// ---------------- problem constants ----------------
#define BATCH  2048
#define HID    512
#define INDIM  128
#define OUTDIM 128
#define SEQ    128
#define RING   16
#define NT     256

// ---------------- step tiling (mma.sync bf16) ----------------
#define BM 128
#define BN 128              // N cols = 32 hcols x 4 gates (interleaved)
#define BKE 32              // K elements per iter
#define NCK (HID / BKE)     // 16
#define ROWB 80             // padded smem row bytes (64 data + 16) -> conflict-free ldmatrix
#define ARR_BYTES (128 * ROWB)      // 10240 per array
#define STG_BYTES (4 * ARR_BYTES)   // AH AL BH BL = 40960 per stage
#define DSMEM_BYTES (2 * STG_BYTES) // 81920

// ---------------- fc tiling (proven R6 kernel) ----------------
#define FBM 64
#define FBK 32
#define FPADN 132

typedef unsigned long long u64;

// ---------------- static device scratch ----------------
__device__ float          g_hring[(size_t)RING * BATCH * HID];   // fp32 h history
__device__ __nv_bfloat16  g_hbh[2 * (size_t)BATCH * HID];        // h bf16 hi, ping-pong
__device__ __nv_bfloat16  g_hbl[2 * (size_t)BATCH * HID];        // h bf16 lo
__device__ __nv_bfloat16  g_W4h[(size_t)4 * HID * HID];          // combined W hi (rows n=4h+g)
__device__ __nv_bfloat16  g_W4l[(size_t)4 * HID * HID];
__device__ __nv_bfloat16  g_W40h[(size_t)4 * HID * HID];         // step-0 variant (x=0)
__device__ __nv_bfloat16  g_W40l[(size_t)4 * HID * HID];
__device__ float          g_b4[4 * HID];
__device__ float          g_b40[4 * HID];

// ---------------- PTX helpers (all baseline sm_80-era; valid on sm_100) ----------------
__device__ __forceinline__ uint32_t smem_u32(const void* p) {
    uint32_t a;
    asm("{ .reg .u64 t; cvta.to.shared.u64 t, %1; cvt.u32.u64 %0, t; }" : "=r"(a) : "l"(p));
    return a;
}
__device__ __forceinline__ void cp16(uint32_t dst, const void* src) {
    asm volatile("cp.async.cg.shared.global [%0], [%1], 16;" :: "r"(dst), "l"(src));
}
__device__ __forceinline__ void cp_commit() {
    asm volatile("cp.async.commit_group;" ::: "memory");
}
__device__ __forceinline__ void cp_wait1() {
    asm volatile("cp.async.wait_group 1;" ::: "memory");
}
__device__ __forceinline__ void cp_wait0() {
    asm volatile("cp.async.wait_group 0;" ::: "memory");
}
__device__ __forceinline__ void ldm_x4(uint32_t* r, uint32_t addr) {
    asm volatile("ldmatrix.sync.aligned.m8n8.x4.shared.b16 {%0,%1,%2,%3}, [%4];"
        : "=r"(r[0]), "=r"(r[1]), "=r"(r[2]), "=r"(r[3]) : "r"(addr));
}
__device__ __forceinline__ void mma_bf16(float* d, const uint32_t* a, const uint32_t* b) {
    asm volatile("mma.sync.aligned.m16n8k16.row.col.f32.bf16.bf16.f32 "
        "{%0,%1,%2,%3}, {%4,%5,%6,%7}, {%8,%9}, {%0,%1,%2,%3};"
        : "+f"(d[0]), "+f"(d[1]), "+f"(d[2]), "+f"(d[3])
        : "r"(a[0]), "r"(a[1]), "r"(a[2]), "r"(a[3]), "r"(b[0]), "r"(b[1]));
}

// ---------------- MUFU-free activations ----------------
__device__ __forceinline__ float fexp(float x) {
    x = fminf(fmaxf(x, -30.0f), 30.0f);
    float y = x * 1.4426950408889634f;
    float m = y + 12582912.0f;
    int   n = __float_as_int(m) - 0x4B400000;
    float f = y - (m - 12582912.0f);
    float p =              1.5403530e-4f;
    p = fmaf(p, f, 1.3333558e-3f);
    p = fmaf(p, f, 9.6181291e-3f);
    p = fmaf(p, f, 5.5504109e-2f);
    p = fmaf(p, f, 2.4022651e-1f);
    p = fmaf(p, f, 6.9314718e-1f);
    p = fmaf(p, f, 1.0f);
    return __int_as_float(__float_as_int(p) + (n << 23));
}
__device__ __forceinline__ float frcp(float d) {
    float x = __int_as_float(0x7EF311C3 - __float_as_int(d));
    x = x * fmaf(-d, x, 2.0f);
    x = x * fmaf(-d, x, 2.0f);
    x = x * fmaf(-d, x, 2.0f);
    return x;
}
__device__ __forceinline__ float fsig(float x)   { return frcp(1.0f + fexp(-x)); }
__device__ __forceinline__ float ftanh_(float y) { return fmaf(2.0f, fsig(2.0f * y), -1.0f); }
__device__ __forceinline__ float gru_comb(float pr, float pz, float pi, float ph, float hp) {
    float r  = fsig(pr);
    float z  = fsig(pz);
    float nn = ftanh_(fmaf(r, ph, pi));
    return fmaf(z, hp - nn, nn);
}

// ---------------- packed f32x2 helpers (fc_batch) ----------------
__device__ __forceinline__ u64 pack2(float lo, float hi) {
    u64 r; asm("mov.b64 %0, {%1, %2};" : "=l"(r) : "f"(lo), "f"(hi)); return r;
}
__device__ __forceinline__ float2 unpack2(u64 v) {
    float2 f; asm("mov.b64 {%0, %1}, %2;" : "=f"(f.x), "=f"(f.y) : "l"(v)); return f;
}
__device__ __forceinline__ u64 fma2(u64 a, u64 b, u64 c) {
    u64 d; asm("fma.rn.f32x2 %0, %1, %2, %3;" : "=l"(d) : "l"(a), "l"(b), "l"(c)); return d;
}

// ---------------- prep: fold FC into recurrent weights; bf16 hi/lo split ----------------
// Row n = hcol*4 + gate (0=R, 1=Z, 2=IN, 3=HN).
__global__ __launch_bounds__(NT)
void prep_w4(const float* __restrict__ w_ih, const float* __restrict__ w_hh,
             const float* __restrict__ fc_w)
{
    const int idx  = blockIdx.x * NT + threadIdx.x;
    const int k    = idx & (HID - 1);
    const int n    = idx >> 9;
    const int hcol = n >> 2;
    const int gate = n & 3;

    float acc = 0.0f;
    if (gate < 3) {
        const int wrow = gate * HID + hcol;
#pragma unroll 8
        for (int o = 0; o < INDIM; ++o)
            acc += w_ih[wrow * INDIM + o] * fc_w[o * HID + k];
    }
    float w4, w40;
    if (gate == 0)      { float w = w_hh[hcol * HID + k];             w4 = acc + w; w40 = w; }
    else if (gate == 1) { float w = w_hh[(HID + hcol) * HID + k];     w4 = acc + w; w40 = w; }
    else if (gate == 2) { w4 = acc; w40 = 0.0f; }
    else                { float w = w_hh[(2 * HID + hcol) * HID + k]; w4 = w;       w40 = w; }

    __nv_bfloat16 h1 = __float2bfloat16_rn(w4);
    g_W4h[idx]  = h1;
    g_W4l[idx]  = __float2bfloat16_rn(w4 - __bfloat162float(h1));
    __nv_bfloat16 h0 = __float2bfloat16_rn(w40);
    g_W40h[idx] = h0;
    g_W40l[idx] = __float2bfloat16_rn(w40 - __bfloat162float(h0));
}

__global__ __launch_bounds__(NT)
void prep_b4(const float* __restrict__ w_ih, const float* __restrict__ b_ih,
             const float* __restrict__ b_hh, const float* __restrict__ fc_b)
{
    const int n    = blockIdx.x * NT + threadIdx.x;
    const int hcol = n >> 2;
    const int gate = n & 3;

    float acc = 0.0f;
    if (gate < 3) {
        const int wrow = gate * HID + hcol;
#pragma unroll 8
        for (int o = 0; o < INDIM; ++o)
            acc += w_ih[wrow * INDIM + o] * fc_b[o];
    }
    float b, b0;
    if (gate == 0)      { b0 = b_ih[hcol] + b_hh[hcol];                 b = acc + b0; }
    else if (gate == 1) { b0 = b_ih[HID + hcol] + b_hh[HID + hcol];     b = acc + b0; }
    else if (gate == 2) { b0 = b_ih[2 * HID + hcol];                    b = acc + b0; }
    else                { b0 = b_hh[2 * HID + hcol];                    b = b0; }
    g_b4[n]  = b;
    g_b40[n] = b0;
}

__global__ __launch_bounds__(NT)
void conv_h0(const float* __restrict__ hsrc)
{
    const int i = blockIdx.x * NT + threadIdx.x;
    const float v = hsrc[i];
    __nv_bfloat16 h16 = __float2bfloat16_rn(v);
    g_hbh[(size_t)BATCH * HID + i] = h16;
    g_hbl[(size_t)BATCH * HID + i] = __float2bfloat16_rn(v - __bfloat162float(h16));
}

// ---------------- mma.sync GRU step ----------------
// grid (16,16), 256 threads (8 warps, 4x2). C[128,128] = Ah*Bh + Ah*Bl + Al*Bh over K=512.
extern __shared__ char dsm[];

__device__ __forceinline__ void issue_stage(
    uint32_t sb, const __nv_bfloat16* Abh, const __nv_bfloat16* Abl,
    const __nv_bfloat16* Wh, const __nv_bfloat16* Wl, int m0, int n0, int ck, int t)
{
    const size_t kof = (size_t)ck * BKE;
#pragma unroll
    for (int rep = 0; rep < 2; ++rep) {
        const int cid = t + (rep << 8);
        const int r = cid >> 2;
        const int c = cid & 3;
        const uint32_t dof = (uint32_t)r * ROWB + c * 16;
        const size_t sof = kof + c * 8;
        cp16(sb + dof,                 Abh + (size_t)(m0 + r) * HID + sof);
        cp16(sb + ARR_BYTES + dof,     Abl + (size_t)(m0 + r) * HID + sof);
        cp16(sb + 2 * ARR_BYTES + dof, Wh  + (size_t)(n0 + r) * HID + sof);
        cp16(sb + 3 * ARR_BYTES + dof, Wl  + (size_t)(n0 + r) * HID + sof);
    }
}

__global__ __launch_bounds__(NT)
void step_kernel(int s, const float* __restrict__ hidden)
{
    const uint32_t sb0 = smem_u32(dsm);

    const int t      = threadIdx.x;
    const int lane   = t & 31;
    const int wid    = t >> 5;
    const int warp_m = wid & 3;       // 32-row chunk
    const int warp_n = wid >> 2;      // 64-col chunk
    const int m0     = blockIdx.x * BM;
    const int n0     = blockIdx.y * BN;

    const __nv_bfloat16* Abh = g_hbh + (size_t)((s + 1) & 1) * BATCH * HID;
    const __nv_bfloat16* Abl = g_hbl + (size_t)((s + 1) & 1) * BATCH * HID;
    const __nv_bfloat16* Wh  = s ? g_W4h : g_W40h;
    const __nv_bfloat16* Wl  = s ? g_W4l : g_W40l;
    const float* bias  = s ? g_b4 : g_b40;
    const float* hprev = (s == 0) ? hidden
                       : (g_hring + (size_t)((s - 1) & (RING - 1)) * BATCH * HID);
    float* hout = g_hring + (size_t)(s & (RING - 1)) * BATCH * HID;
    __nv_bfloat16* hbh_o = g_hbh + (size_t)(s & 1) * BATCH * HID;
    __nv_bfloat16* hbl_o = g_hbl + (size_t)(s & 1) * BATCH * HID;

    float acc[2][8][4];
#pragma unroll
    for (int mt = 0; mt < 2; ++mt)
#pragma unroll
        for (int nt = 0; nt < 8; ++nt)
#pragma unroll
            for (int e = 0; e < 4; ++e) acc[mt][nt][e] = 0.0f;

    // prologue: stage 0 <- ck 0
    issue_stage(sb0, Abh, Abl, Wh, Wl, m0, n0, 0, t);
    cp_commit();

    for (int ck = 0; ck < NCK; ++ck) {
        if (ck < NCK - 1) {
            issue_stage(sb0 + ((ck + 1) & 1) * STG_BYTES, Abh, Abl, Wh, Wl, m0, n0, ck + 1, t);
            cp_commit();
            cp_wait1();
        } else {
            cp_wait0();
        }
        __syncthreads();

        const uint32_t sbs = sb0 + (ck & 1) * STG_BYTES;
#pragma unroll
        for (int ks = 0; ks < 2; ++ks) {
            // A fragments (hi & lo) for two m16 tiles
            const uint32_t aA = sbs + (uint32_t)(warp_m * 32 + (lane & 15)) * ROWB
                              + (uint32_t)(ks * 2 + (lane >> 4)) * 16;
            uint32_t Ah[2][4], Al[2][4];
            ldm_x4(Ah[0], aA);
            ldm_x4(Ah[1], aA + 16 * ROWB);
            ldm_x4(Al[0], aA + ARR_BYTES);
            ldm_x4(Al[1], aA + ARR_BYTES + 16 * ROWB);

#pragma unroll
            for (int p = 0; p < 4; ++p) {
                const uint32_t rB = (uint32_t)(warp_n * 64 + p * 16 + (lane & 7)
                                  + ((lane >> 4) & 1) * 8);
                const uint32_t aB = sbs + 2 * ARR_BYTES + rB * ROWB
                                  + (uint32_t)(ks * 2 + ((lane >> 3) & 1)) * 16;
                uint32_t Bh[4], Bl[4];
                ldm_x4(Bh, aB);
                ldm_x4(Bl, aB + ARR_BYTES);
#pragma unroll
                for (int mt = 0; mt < 2; ++mt) {
#pragma unroll
                    for (int hf = 0; hf < 2; ++hf) {
                        float* d = acc[mt][p * 2 + hf];
                        mma_bf16(d, Ah[mt], Bh + hf * 2);   // Ah*Bh
                        mma_bf16(d, Ah[mt], Bl + hf * 2);   // Ah*Bl
                        mma_bf16(d, Al[mt], Bh + hf * 2);   // Al*Bh
                    }
                }
            }
        }
        __syncthreads();
    }

    // ---- epilogue: reunite gates via shfl, combine, stage, coalesced writeout ----
    float* stg = reinterpret_cast<float*>(dsm);   // 128 x 33 floats (reuses stage 0)
    const int lq  = lane >> 2;
    const int lr4 = lane & 3;
    const int hb  = n0 >> 2;                      // block's first hcol

#pragma unroll
    for (int mt = 0; mt < 2; ++mt) {
#pragma unroll
        for (int nt = 0; nt < 8; ++nt) {
            float* a = acc[mt][nt];
            // even lane (lr4 even): holds (r,z) rows r0,r0+8; odd: (in,hn)
            float sv0 = (lane & 1) ? a[0] : a[2];
            float rv0 = __shfl_xor_sync(0xffffffffu, sv0, 1);
            float sv1 = (lane & 1) ? a[1] : a[3];
            float rv1 = __shfl_xor_sync(0xffffffffu, sv1, 1);
            float gr, gz, gi, gh_;
            if (!(lane & 1)) { gr = a[0]; gz = a[1]; gi = rv0;  gh_ = rv1;  }
            else             { gr = rv0;  gz = rv1;  gi = a[2]; gh_ = a[3]; }
            const int rl = warp_m * 32 + mt * 16 + lq + ((lane & 1) << 3);
            const int c0 = n0 + warp_n * 64 + nt * 8 + lr4 * 2;
            const int hg = c0 >> 2;
            const float4 bb = *reinterpret_cast<const float4*>(&bias[hg << 2]);
            const float hp = hprev[(size_t)(m0 + rl) * HID + hg];
            stg[rl * 33 + (hg - hb)] =
                gru_comb(gr + bb.x, gz + bb.y, gi + bb.z, gh_ + bb.w, hp);
        }
    }
    __syncthreads();

    {
        const int row  = t >> 1;
        const int half = t & 1;
        float v[16];
#pragma unroll
        for (int i = 0; i < 16; ++i) v[i] = stg[row * 33 + half * 16 + i];
        const size_t ro = (size_t)(m0 + row) * HID + hb + half * 16;
#pragma unroll
        for (int q = 0; q < 4; ++q)
            *reinterpret_cast<float4*>(&hout[ro + q * 4]) =
                make_float4(v[q * 4], v[q * 4 + 1], v[q * 4 + 2], v[q * 4 + 3]);
        uint32_t hw[8], lw[8];
#pragma unroll
        for (int i = 0; i < 8; ++i) {
            __nv_bfloat16 a0 = __float2bfloat16_rn(v[2 * i]);
            __nv_bfloat16 a1 = __float2bfloat16_rn(v[2 * i + 1]);
            __nv_bfloat16 b0 = __float2bfloat16_rn(v[2 * i]     - __bfloat162float(a0));
            __nv_bfloat16 b1 = __float2bfloat16_rn(v[2 * i + 1] - __bfloat162float(a1));
            hw[i] = (uint32_t)__bfloat16_as_ushort(a0) | ((uint32_t)__bfloat16_as_ushort(a1) << 16);
            lw[i] = (uint32_t)__bfloat16_as_ushort(b0) | ((uint32_t)__bfloat16_as_ushort(b1) << 16);
        }
        *reinterpret_cast<uint4*>(hbh_o + ro)     = make_uint4(hw[0], hw[1], hw[2], hw[3]);
        *reinterpret_cast<uint4*>(hbh_o + ro + 8) = make_uint4(hw[4], hw[5], hw[6], hw[7]);
        *reinterpret_cast<uint4*>(hbl_o + ro)     = make_uint4(lw[0], lw[1], lw[2], lw[3]);
        *reinterpret_cast<uint4*>(hbl_o + ro + 8) = make_uint4(lw[4], lw[5], lw[6], lw[7]);
    }
}

// ---------------- batched FC over RING steps (proven R6 kernel) ----------------
__global__ __launch_bounds__(NT)
void fc_batch(int s0, const float* __restrict__ fc_w, const float* __restrict__ fc_b,
              float* __restrict__ out)
{
    __shared__ __align__(16) u64   As2[FBK * FBM];
    __shared__ __align__(16) float Bs[FBK * FPADN];

    const int r0 = blockIdx.x * FBM;
    const int t  = threadIdx.x;
    const int tx = t & 15;
    const int ty = t >> 4;
    const int arow = t >> 2;
    const int acg  = (t & 3) << 3;
    const int brow = t >> 1;
    const int bcg  = (t & 1) << 4;

    u64 acc[4][4];
#pragma unroll
    for (int i = 0; i < 4; ++i)
#pragma unroll
        for (int p = 0; p < 4; ++p) acc[i][p] = 0ull;

    for (int kb = 0; kb < HID; kb += FBK) {
        {
            const float4* ap = reinterpret_cast<const float4*>(
                &g_hring[(size_t)(r0 + arow) * HID + kb + acg]);
            const float4 a0 = ap[0], a1 = ap[1];
            As2[(acg + 0) * FBM + arow] = pack2(a0.x, a0.x);
            As2[(acg + 1) * FBM + arow] = pack2(a0.y, a0.y);
            As2[(acg + 2) * FBM + arow] = pack2(a0.z, a0.z);
            As2[(acg + 3) * FBM + arow] = pack2(a0.w, a0.w);
            As2[(acg + 4) * FBM + arow] = pack2(a1.x, a1.x);
            As2[(acg + 5) * FBM + arow] = pack2(a1.y, a1.y);
            As2[(acg + 6) * FBM + arow] = pack2(a1.z, a1.z);
            As2[(acg + 7) * FBM + arow] = pack2(a1.w, a1.w);
        }
        {
            const float4* bp = reinterpret_cast<const float4*>(
                &fc_w[(size_t)brow * HID + kb + bcg]);
            const float4 b0 = bp[0], b1 = bp[1], b2 = bp[2], b3 = bp[3];
            Bs[(bcg +  0) * FPADN + brow] = b0.x;
            Bs[(bcg +  1) * FPADN + brow] = b0.y;
            Bs[(bcg +  2) * FPADN + brow] = b0.z;
            Bs[(bcg +  3) * FPADN + brow] = b0.w;
            Bs[(bcg +  4) * FPADN + brow] = b1.x;
            Bs[(bcg +  5) * FPADN + brow] = b1.y;
            Bs[(bcg +  6) * FPADN + brow] = b1.z;
            Bs[(bcg +  7) * FPADN + brow] = b1.w;
            Bs[(bcg +  8) * FPADN + brow] = b2.x;
            Bs[(bcg +  9) * FPADN + brow] = b2.y;
            Bs[(bcg + 10) * FPADN + brow] = b2.z;
            Bs[(bcg + 11) * FPADN + brow] = b2.w;
            Bs[(bcg + 12) * FPADN + brow] = b3.x;
            Bs[(bcg + 13) * FPADN + brow] = b3.y;
            Bs[(bcg + 14) * FPADN + brow] = b3.z;
            Bs[(bcg + 15) * FPADN + brow] = b3.w;
        }
        __syncthreads();

#pragma unroll
        for (int kk = 0; kk < FBK; ++kk) {
            const ulonglong2 a01 = *reinterpret_cast<const ulonglong2*>(&As2[kk * FBM + (ty << 2)]);
            const ulonglong2 a23 = *reinterpret_cast<const ulonglong2*>(&As2[kk * FBM + (ty << 2) + 2]);
            const ulonglong2 bv0 = *reinterpret_cast<const ulonglong2*>(&Bs[(size_t)kk * FPADN + (tx << 3)]);
            const ulonglong2 bv1 = *reinterpret_cast<const ulonglong2*>(&Bs[(size_t)kk * FPADN + (tx << 3) + 4]);
            acc[0][0] = fma2(a01.x, bv0.x, acc[0][0]);
            acc[0][1] = fma2(a01.x, bv0.y, acc[0][1]);
            acc[0][2] = fma2(a01.x, bv1.x, acc[0][2]);
            acc[0][3] = fma2(a01.x, bv1.y, acc[0][3]);
            acc[1][0] = fma2(a01.y, bv0.x, acc[1][0]);
            acc[1][1] = fma2(a01.y, bv0.y, acc[1][1]);
            acc[1][2] = fma2(a01.y, bv1.x, acc[1][2]);
            acc[1][3] = fma2(a01.y, bv1.y, acc[1][3]);
            acc[2][0] = fma2(a23.x, bv0.x, acc[2][0]);
            acc[2][1] = fma2(a23.x, bv0.y, acc[2][1]);
            acc[2][2] = fma2(a23.x, bv1.x, acc[2][2]);
            acc[2][3] = fma2(a23.x, bv1.y, acc[2][3]);
            acc[3][0] = fma2(a23.y, bv0.x, acc[3][0]);
            acc[3][1] = fma2(a23.y, bv0.y, acc[3][1]);
            acc[3][2] = fma2(a23.y, bv1.x, acc[3][2]);
            acc[3][3] = fma2(a23.y, bv1.y, acc[3][3]);
        }
        __syncthreads();
    }

    const int col = tx << 3;
    const float4 fb0 = *reinterpret_cast<const float4*>(&fc_b[col]);
    const float4 fb1 = *reinterpret_cast<const float4*>(&fc_b[col + 4]);

#pragma unroll
    for (int i = 0; i < 4; ++i) {
        const int r = r0 + (ty << 2) + i;
        const int s = s0 + (r >> 11);
        const int b = r & (BATCH - 1);
        float* dst = out + (size_t)b * SEQ * OUTDIM + (size_t)(SEQ - 1 - s) * OUTDIM + col;
        const float2 p0 = unpack2(acc[i][0]);
        const float2 p1 = unpack2(acc[i][1]);
        const float2 p2 = unpack2(acc[i][2]);
        const float2 p3 = unpack2(acc[i][3]);
        float4 o0, o1;
        o0.x = p0.x + fb0.x; o0.y = p0.y + fb0.y; o0.z = p1.x + fb0.z; o0.w = p1.y + fb0.w;
        o1.x = p2.x + fb1.x; o1.y = p2.y + fb1.y; o1.z = p3.x + fb1.z; o1.w = p3.y + fb1.w;
        *reinterpret_cast<float4*>(dst)     = o0;
        *reinterpret_cast<float4*>(dst + 4) = o1;
    }
}

// ---------------- launch ----------------
// inputs: hidden, w_ih, w_hh, b_ih, b_hh, fc_w, fc_b, seq_len
extern "C" void kernel_launch(void* const* d_in, const int* in_sizes, int n_in,
                              void* d_out, int out_size)
{
    const float* hidden = (const float*)d_in[0];
    const float* w_ih   = (const float*)d_in[1];
    const float* w_hh   = (const float*)d_in[2];
    const float* b_ih   = (const float*)d_in[3];
    const float* b_hh   = (const float*)d_in[4];
    const float* fc_w   = (const float*)d_in[5];
    const float* fc_b   = (const float*)d_in[6];
    float* out = (float*)d_out;

    cudaFuncSetAttribute(step_kernel, cudaFuncAttributeMaxDynamicSharedMemorySize, DSMEM_BYTES);

    prep_w4<<<(4 * HID * HID) / NT, NT>>>(w_ih, w_hh, fc_w);
    prep_b4<<<(4 * HID) / NT, NT>>>(w_ih, b_ih, b_hh, fc_b);
    conv_h0<<<(BATCH * HID) / NT, NT>>>(hidden);

    const dim3 gridS(BATCH / BM, (4 * HID) / BN);     // 16 x 16
    for (int s = 0; s < SEQ; ++s) {
        step_kernel<<<gridS, NT, DSMEM_BYTES>>>(s, hidden);
        if ((s & (RING - 1)) == RING - 1)
            fc_batch<<<RING * BATCH / FBM, NT>>>(s - RING + 1, fc_w, fc_b, out);
    }
}

// round 10
// speedup vs baseline: 2.4141x; 1.0849x over previous
#include <cuda_runtime.h>
#include <cuda_bf16.h>
#include <math.h>
#include <stdint.h>

// ---------------- problem constants ----------------
#define BATCH  2048
#define HID    512
#define INDIM  128
#define OUTDIM 128
#define SEQ    128
#define RING   16
#define NT     256

// ---------------- step tiling (mma.sync bf16) ----------------
#define BM 128
#define BN 128              // N cols = 32 hcols x 4 gates (interleaved)
#define BKE 32              // K elements per iter
#define NCK (HID / BKE)     // 16
#define ROWB 80             // padded smem row bytes (64 data + 16) -> conflict-free ldmatrix
#define ARR_BYTES (128 * ROWB)      // 10240 per array
#define STG_BYTES (4 * ARR_BYTES)   // AH AL BH BL = 40960 per stage
#define DSMEM_BYTES (2 * STG_BYTES) // 81920

// ---------------- fc tiling (proven R6 kernel) ----------------
#define FBM 64
#define FBK 32
#define FPADN 132

typedef unsigned long long u64;

// ---------------- static device scratch ----------------
__device__ float          g_hring[(size_t)RING * BATCH * HID];   // fp32 h history
__device__ __nv_bfloat16  g_hbh[2 * (size_t)BATCH * HID];        // h bf16 hi, ping-pong
__device__ __nv_bfloat16  g_hbl[2 * (size_t)BATCH * HID];        // h bf16 lo
__device__ __nv_bfloat16  g_W4h[(size_t)4 * HID * HID];          // combined W hi (rows n=4h+g)
__device__ __nv_bfloat16  g_W4l[(size_t)4 * HID * HID];
__device__ __nv_bfloat16  g_W40h[(size_t)4 * HID * HID];         // step-0 variant (x=0)
__device__ __nv_bfloat16  g_W40l[(size_t)4 * HID * HID];
__device__ float          g_b4[4 * HID];
__device__ float          g_b40[4 * HID];

// ---------------- PTX helpers (all baseline sm_80-era; valid on sm_100) ----------------
__device__ __forceinline__ uint32_t smem_u32(const void* p) {
    uint32_t a;
    asm("{ .reg .u64 t; cvta.to.shared.u64 t, %1; cvt.u32.u64 %0, t; }" : "=r"(a) : "l"(p));
    return a;
}
__device__ __forceinline__ void cp16(uint32_t dst, const void* src) {
    asm volatile("cp.async.cg.shared.global [%0], [%1], 16;" :: "r"(dst), "l"(src));
}
__device__ __forceinline__ void cp_commit() {
    asm volatile("cp.async.commit_group;" ::: "memory");
}
__device__ __forceinline__ void cp_wait1() {
    asm volatile("cp.async.wait_group 1;" ::: "memory");
}
__device__ __forceinline__ void cp_wait0() {
    asm volatile("cp.async.wait_group 0;" ::: "memory");
}
__device__ __forceinline__ void ldm_x4(uint32_t* r, uint32_t addr) {
    asm volatile("ldmatrix.sync.aligned.m8n8.x4.shared.b16 {%0,%1,%2,%3}, [%4];"
        : "=r"(r[0]), "=r"(r[1]), "=r"(r[2]), "=r"(r[3]) : "r"(addr));
}
__device__ __forceinline__ void mma_bf16(float* d, const uint32_t* a, const uint32_t* b) {
    asm volatile("mma.sync.aligned.m16n8k16.row.col.f32.bf16.bf16.f32 "
        "{%0,%1,%2,%3}, {%4,%5,%6,%7}, {%8,%9}, {%0,%1,%2,%3};"
        : "+f"(d[0]), "+f"(d[1]), "+f"(d[2]), "+f"(d[3])
        : "r"(a[0]), "r"(a[1]), "r"(a[2]), "r"(a[3]), "r"(b[0]), "r"(b[1]));
}

// ---------------- MUFU-free activations ----------------
__device__ __forceinline__ float fexp(float x) {
    x = fminf(fmaxf(x, -30.0f), 30.0f);
    float y = x * 1.4426950408889634f;
    float m = y + 12582912.0f;
    int   n = __float_as_int(m) - 0x4B400000;
    float f = y - (m - 12582912.0f);
    float p =              1.5403530e-4f;
    p = fmaf(p, f, 1.3333558e-3f);
    p = fmaf(p, f, 9.6181291e-3f);
    p = fmaf(p, f, 5.5504109e-2f);
    p = fmaf(p, f, 2.4022651e-1f);
    p = fmaf(p, f, 6.9314718e-1f);
    p = fmaf(p, f, 1.0f);
    return __int_as_float(__float_as_int(p) + (n << 23));
}
__device__ __forceinline__ float frcp(float d) {
    float x = __int_as_float(0x7EF311C3 - __float_as_int(d));
    x = x * fmaf(-d, x, 2.0f);
    x = x * fmaf(-d, x, 2.0f);
    x = x * fmaf(-d, x, 2.0f);
    return x;
}
__device__ __forceinline__ float fsig(float x)   { return frcp(1.0f + fexp(-x)); }
__device__ __forceinline__ float ftanh_(float y) { return fmaf(2.0f, fsig(2.0f * y), -1.0f); }
__device__ __forceinline__ float gru_comb(float pr, float pz, float pi, float ph, float hp) {
    float r  = fsig(pr);
    float z  = fsig(pz);
    float nn = ftanh_(fmaf(r, ph, pi));
    return fmaf(z, hp - nn, nn);
}

// ---------------- packed f32x2 helpers (fc_batch) ----------------
__device__ __forceinline__ u64 pack2(float lo, float hi) {
    u64 r; asm("mov.b64 %0, {%1, %2};" : "=l"(r) : "f"(lo), "f"(hi)); return r;
}
__device__ __forceinline__ float2 unpack2(u64 v) {
    float2 f; asm("mov.b64 {%0, %1}, %2;" : "=f"(f.x), "=f"(f.y) : "l"(v)); return f;
}
__device__ __forceinline__ u64 fma2(u64 a, u64 b, u64 c) {
    u64 d; asm("fma.rn.f32x2 %0, %1, %2, %3;" : "=l"(d) : "l"(a), "l"(b), "l"(c)); return d;
}

// ---------------- prep: fold FC into recurrent weights; bf16 hi/lo split ----------------
// Row n = hcol*4 + gate (0=R, 1=Z, 2=IN, 3=HN).
__global__ __launch_bounds__(NT)
void prep_w4(const float* __restrict__ w_ih, const float* __restrict__ w_hh,
             const float* __restrict__ fc_w)
{
    const int idx  = blockIdx.x * NT + threadIdx.x;
    const int k    = idx & (HID - 1);
    const int n    = idx >> 9;
    const int hcol = n >> 2;
    const int gate = n & 3;

    float acc = 0.0f;
    if (gate < 3) {
        const int wrow = gate * HID + hcol;
#pragma unroll 8
        for (int o = 0; o < INDIM; ++o)
            acc += w_ih[wrow * INDIM + o] * fc_w[o * HID + k];
    }
    float w4, w40;
    if (gate == 0)      { float w = w_hh[hcol * HID + k];             w4 = acc + w; w40 = w; }
    else if (gate == 1) { float w = w_hh[(HID + hcol) * HID + k];     w4 = acc + w; w40 = w; }
    else if (gate == 2) { w4 = acc; w40 = 0.0f; }
    else                { float w = w_hh[(2 * HID + hcol) * HID + k]; w4 = w;       w40 = w; }

    __nv_bfloat16 h1 = __float2bfloat16_rn(w4);
    g_W4h[idx]  = h1;
    g_W4l[idx]  = __float2bfloat16_rn(w4 - __bfloat162float(h1));
    __nv_bfloat16 h0 = __float2bfloat16_rn(w40);
    g_W40h[idx] = h0;
    g_W40l[idx] = __float2bfloat16_rn(w40 - __bfloat162float(h0));
}

__global__ __launch_bounds__(NT)
void prep_b4(const float* __restrict__ w_ih, const float* __restrict__ b_ih,
             const float* __restrict__ b_hh, const float* __restrict__ fc_b)
{
    const int n    = blockIdx.x * NT + threadIdx.x;
    const int hcol = n >> 2;
    const int gate = n & 3;

    float acc = 0.0f;
    if (gate < 3) {
        const int wrow = gate * HID + hcol;
#pragma unroll 8
        for (int o = 0; o < INDIM; ++o)
            acc += w_ih[wrow * INDIM + o] * fc_b[o];
    }
    float b, b0;
    if (gate == 0)      { b0 = b_ih[hcol] + b_hh[hcol];                 b = acc + b0; }
    else if (gate == 1) { b0 = b_ih[HID + hcol] + b_hh[HID + hcol];     b = acc + b0; }
    else if (gate == 2) { b0 = b_ih[2 * HID + hcol];                    b = acc + b0; }
    else                { b0 = b_hh[2 * HID + hcol];                    b = b0; }
    g_b4[n]  = b;
    g_b40[n] = b0;
}

__global__ __launch_bounds__(NT)
void conv_h0(const float* __restrict__ hsrc)
{
    const int i = blockIdx.x * NT + threadIdx.x;
    const float v = hsrc[i];
    __nv_bfloat16 h16 = __float2bfloat16_rn(v);
    g_hbh[(size_t)BATCH * HID + i] = h16;
    g_hbl[(size_t)BATCH * HID + i] = __float2bfloat16_rn(v - __bfloat162float(h16));
}

// ---------------- mma.sync GRU step ----------------
// grid (16,16), 256 threads (8 warps, 4x2). C[128,128] = Ah*Bh + Ah*Bl + Al*Bh over K=512.
// __launch_bounds__(NT, 2): cap regs at 128 -> 2 CTAs/SM -> 256 CTAs in ONE wave.
extern __shared__ char dsm[];

__device__ __forceinline__ void issue_stage(
    uint32_t sb, const __nv_bfloat16* Abh, const __nv_bfloat16* Abl,
    const __nv_bfloat16* Wh, const __nv_bfloat16* Wl, int m0, int n0, int ck, int t)
{
    const size_t kof = (size_t)ck * BKE;
#pragma unroll
    for (int rep = 0; rep < 2; ++rep) {
        const int cid = t + (rep << 8);
        const int r = cid >> 2;
        const int c = cid & 3;
        const uint32_t dof = (uint32_t)r * ROWB + c * 16;
        const size_t sof = kof + c * 8;
        cp16(sb + dof,                 Abh + (size_t)(m0 + r) * HID + sof);
        cp16(sb + ARR_BYTES + dof,     Abl + (size_t)(m0 + r) * HID + sof);
        cp16(sb + 2 * ARR_BYTES + dof, Wh  + (size_t)(n0 + r) * HID + sof);
        cp16(sb + 3 * ARR_BYTES + dof, Wl  + (size_t)(n0 + r) * HID + sof);
    }
}

__global__ __launch_bounds__(NT, 2)
void step_kernel(int s, const float* __restrict__ hidden)
{
    const uint32_t sb0 = smem_u32(dsm);

    const int t      = threadIdx.x;
    const int lane   = t & 31;
    const int wid    = t >> 5;
    const int warp_m = wid & 3;       // 32-row chunk
    const int warp_n = wid >> 2;      // 64-col chunk
    const int m0     = blockIdx.x * BM;
    const int n0     = blockIdx.y * BN;

    const __nv_bfloat16* Abh = g_hbh + (size_t)((s + 1) & 1) * BATCH * HID;
    const __nv_bfloat16* Abl = g_hbl + (size_t)((s + 1) & 1) * BATCH * HID;
    const __nv_bfloat16* Wh  = s ? g_W4h : g_W40h;
    const __nv_bfloat16* Wl  = s ? g_W4l : g_W40l;
    const float* bias  = s ? g_b4 : g_b40;
    const float* hprev = (s == 0) ? hidden
                       : (g_hring + (size_t)((s - 1) & (RING - 1)) * BATCH * HID);
    float* hout = g_hring + (size_t)(s & (RING - 1)) * BATCH * HID;
    __nv_bfloat16* hbh_o = g_hbh + (size_t)(s & 1) * BATCH * HID;
    __nv_bfloat16* hbl_o = g_hbl + (size_t)(s & 1) * BATCH * HID;

    float acc[2][8][4];
#pragma unroll
    for (int mt = 0; mt < 2; ++mt)
#pragma unroll
        for (int nt = 0; nt < 8; ++nt)
#pragma unroll
            for (int e = 0; e < 4; ++e) acc[mt][nt][e] = 0.0f;

    // prologue: stage 0 <- ck 0
    issue_stage(sb0, Abh, Abl, Wh, Wl, m0, n0, 0, t);
    cp_commit();

    for (int ck = 0; ck < NCK; ++ck) {
        if (ck < NCK - 1) {
            issue_stage(sb0 + ((ck + 1) & 1) * STG_BYTES, Abh, Abl, Wh, Wl, m0, n0, ck + 1, t);
            cp_commit();
            cp_wait1();
        } else {
            cp_wait0();
        }
        __syncthreads();

        const uint32_t sbs = sb0 + (ck & 1) * STG_BYTES;
#pragma unroll
        for (int ks = 0; ks < 2; ++ks) {
            // A fragments (hi & lo) for two m16 tiles
            const uint32_t aA = sbs + (uint32_t)(warp_m * 32 + (lane & 15)) * ROWB
                              + (uint32_t)(ks * 2 + (lane >> 4)) * 16;
            uint32_t Ah[2][4], Al[2][4];
            ldm_x4(Ah[0], aA);
            ldm_x4(Ah[1], aA + 16 * ROWB);
            ldm_x4(Al[0], aA + ARR_BYTES);
            ldm_x4(Al[1], aA + ARR_BYTES + 16 * ROWB);

#pragma unroll
            for (int p = 0; p < 4; ++p) {
                const uint32_t rB = (uint32_t)(warp_n * 64 + p * 16 + (lane & 7)
                                  + ((lane >> 4) & 1) * 8);
                const uint32_t aB = sbs + 2 * ARR_BYTES + rB * ROWB
                                  + (uint32_t)(ks * 2 + ((lane >> 3) & 1)) * 16;
                uint32_t Bh[4], Bl[4];
                ldm_x4(Bh, aB);
                ldm_x4(Bl, aB + ARR_BYTES);
#pragma unroll
                for (int mt = 0; mt < 2; ++mt) {
#pragma unroll
                    for (int hf = 0; hf < 2; ++hf) {
                        float* d = acc[mt][p * 2 + hf];
                        mma_bf16(d, Ah[mt], Bh + hf * 2);   // Ah*Bh
                        mma_bf16(d, Ah[mt], Bl + hf * 2);   // Ah*Bl
                        mma_bf16(d, Al[mt], Bh + hf * 2);   // Al*Bh
                    }
                }
            }
        }
        __syncthreads();
    }

    // ---- epilogue: reunite gates via shfl, combine, stage, coalesced writeout ----
    float* stg = reinterpret_cast<float*>(dsm);   // 128 x 33 floats (reuses stage 0)
    const int lq  = lane >> 2;
    const int lr4 = lane & 3;
    const int hb  = n0 >> 2;                      // block's first hcol

#pragma unroll
    for (int mt = 0; mt < 2; ++mt) {
#pragma unroll
        for (int nt = 0; nt < 8; ++nt) {
            float* a = acc[mt][nt];
            // even lane (lr4 even): holds (r,z) rows r0,r0+8; odd: (in,hn)
            float sv0 = (lane & 1) ? a[0] : a[2];
            float rv0 = __shfl_xor_sync(0xffffffffu, sv0, 1);
            float sv1 = (lane & 1) ? a[1] : a[3];
            float rv1 = __shfl_xor_sync(0xffffffffu, sv1, 1);
            float gr, gz, gi, gh_;
            if (!(lane & 1)) { gr = a[0]; gz = a[1]; gi = rv0;  gh_ = rv1;  }
            else             { gr = rv0;  gz = rv1;  gi = a[2]; gh_ = a[3]; }
            const int rl = warp_m * 32 + mt * 16 + lq + ((lane & 1) << 3);
            const int c0 = n0 + warp_n * 64 + nt * 8 + lr4 * 2;
            const int hg = c0 >> 2;
            const float4 bb = *reinterpret_cast<const float4*>(&bias[hg << 2]);
            const float hp = hprev[(size_t)(m0 + rl) * HID + hg];
            stg[rl * 33 + (hg - hb)] =
                gru_comb(gr + bb.x, gz + bb.y, gi + bb.z, gh_ + bb.w, hp);
        }
    }
    __syncthreads();

    {
        const int row  = t >> 1;
        const int half = t & 1;
        float v[16];
#pragma unroll
        for (int i = 0; i < 16; ++i) v[i] = stg[row * 33 + half * 16 + i];
        const size_t ro = (size_t)(m0 + row) * HID + hb + half * 16;
#pragma unroll
        for (int q = 0; q < 4; ++q)
            *reinterpret_cast<float4*>(&hout[ro + q * 4]) =
                make_float4(v[q * 4], v[q * 4 + 1], v[q * 4 + 2], v[q * 4 + 3]);
        uint32_t hw[8], lw[8];
#pragma unroll
        for (int i = 0; i < 8; ++i) {
            __nv_bfloat16 a0 = __float2bfloat16_rn(v[2 * i]);
            __nv_bfloat16 a1 = __float2bfloat16_rn(v[2 * i + 1]);
            __nv_bfloat16 b0 = __float2bfloat16_rn(v[2 * i]     - __bfloat162float(a0));
            __nv_bfloat16 b1 = __float2bfloat16_rn(v[2 * i + 1] - __bfloat162float(a1));
            hw[i] = (uint32_t)__bfloat16_as_ushort(a0) | ((uint32_t)__bfloat16_as_ushort(a1) << 16);
            lw[i] = (uint32_t)__bfloat16_as_ushort(b0) | ((uint32_t)__bfloat16_as_ushort(b1) << 16);
        }
        *reinterpret_cast<uint4*>(hbh_o + ro)     = make_uint4(hw[0], hw[1], hw[2], hw[3]);
        *reinterpret_cast<uint4*>(hbh_o + ro + 8) = make_uint4(hw[4], hw[5], hw[6], hw[7]);
        *reinterpret_cast<uint4*>(hbl_o + ro)     = make_uint4(lw[0], lw[1], lw[2], lw[3]);
        *reinterpret_cast<uint4*>(hbl_o + ro + 8) = make_uint4(lw[4], lw[5], lw[6], lw[7]);
    }
}

// ---------------- batched FC over RING steps (proven R6 kernel) ----------------
__global__ __launch_bounds__(NT)
void fc_batch(int s0, const float* __restrict__ fc_w, const float* __restrict__ fc_b,
              float* __restrict__ out)
{
    __shared__ __align__(16) u64   As2[FBK * FBM];
    __shared__ __align__(16) float Bs[FBK * FPADN];

    const int r0 = blockIdx.x * FBM;
    const int t  = threadIdx.x;
    const int tx = t & 15;
    const int ty = t >> 4;
    const int arow = t >> 2;
    const int acg  = (t & 3) << 3;
    const int brow = t >> 1;
    const int bcg  = (t & 1) << 4;

    u64 acc[4][4];
#pragma unroll
    for (int i = 0; i < 4; ++i)
#pragma unroll
        for (int p = 0; p < 4; ++p) acc[i][p] = 0ull;

    for (int kb = 0; kb < HID; kb += FBK) {
        {
            const float4* ap = reinterpret_cast<const float4*>(
                &g_hring[(size_t)(r0 + arow) * HID + kb + acg]);
            const float4 a0 = ap[0], a1 = ap[1];
            As2[(acg + 0) * FBM + arow] = pack2(a0.x, a0.x);
            As2[(acg + 1) * FBM + arow] = pack2(a0.y, a0.y);
            As2[(acg + 2) * FBM + arow] = pack2(a0.z, a0.z);
            As2[(acg + 3) * FBM + arow] = pack2(a0.w, a0.w);
            As2[(acg + 4) * FBM + arow] = pack2(a1.x, a1.x);
            As2[(acg + 5) * FBM + arow] = pack2(a1.y, a1.y);
            As2[(acg + 6) * FBM + arow] = pack2(a1.z, a1.z);
            As2[(acg + 7) * FBM + arow] = pack2(a1.w, a1.w);
        }
        {
            const float4* bp = reinterpret_cast<const float4*>(
                &fc_w[(size_t)brow * HID + kb + bcg]);
            const float4 b0 = bp[0], b1 = bp[1], b2 = bp[2], b3 = bp[3];
            Bs[(bcg +  0) * FPADN + brow] = b0.x;
            Bs[(bcg +  1) * FPADN + brow] = b0.y;
            Bs[(bcg +  2) * FPADN + brow] = b0.z;
            Bs[(bcg +  3) * FPADN + brow] = b0.w;
            Bs[(bcg +  4) * FPADN + brow] = b1.x;
            Bs[(bcg +  5) * FPADN + brow] = b1.y;
            Bs[(bcg +  6) * FPADN + brow] = b1.z;
            Bs[(bcg +  7) * FPADN + brow] = b1.w;
            Bs[(bcg +  8) * FPADN + brow] = b2.x;
            Bs[(bcg +  9) * FPADN + brow] = b2.y;
            Bs[(bcg + 10) * FPADN + brow] = b2.z;
            Bs[(bcg + 11) * FPADN + brow] = b2.w;
            Bs[(bcg + 12) * FPADN + brow] = b3.x;
            Bs[(bcg + 13) * FPADN + brow] = b3.y;
            Bs[(bcg + 14) * FPADN + brow] = b3.z;
            Bs[(bcg + 15) * FPADN + brow] = b3.w;
        }
        __syncthreads();

#pragma unroll
        for (int kk = 0; kk < FBK; ++kk) {
            const ulonglong2 a01 = *reinterpret_cast<const ulonglong2*>(&As2[kk * FBM + (ty << 2)]);
            const ulonglong2 a23 = *reinterpret_cast<const ulonglong2*>(&As2[kk * FBM + (ty << 2) + 2]);
            const ulonglong2 bv0 = *reinterpret_cast<const ulonglong2*>(&Bs[(size_t)kk * FPADN + (tx << 3)]);
            const ulonglong2 bv1 = *reinterpret_cast<const ulonglong2*>(&Bs[(size_t)kk * FPADN + (tx << 3) + 4]);
            acc[0][0] = fma2(a01.x, bv0.x, acc[0][0]);
            acc[0][1] = fma2(a01.x, bv0.y, acc[0][1]);
            acc[0][2] = fma2(a01.x, bv1.x, acc[0][2]);
            acc[0][3] = fma2(a01.x, bv1.y, acc[0][3]);
            acc[1][0] = fma2(a01.y, bv0.x, acc[1][0]);
            acc[1][1] = fma2(a01.y, bv0.y, acc[1][1]);
            acc[1][2] = fma2(a01.y, bv1.x, acc[1][2]);
            acc[1][3] = fma2(a01.y, bv1.y, acc[1][3]);
            acc[2][0] = fma2(a23.x, bv0.x, acc[2][0]);
            acc[2][1] = fma2(a23.x, bv0.y, acc[2][1]);
            acc[2][2] = fma2(a23.x, bv1.x, acc[2][2]);
            acc[2][3] = fma2(a23.x, bv1.y, acc[2][3]);
            acc[3][0] = fma2(a23.y, bv0.x, acc[3][0]);
            acc[3][1] = fma2(a23.y, bv0.y, acc[3][1]);
            acc[3][2] = fma2(a23.y, bv1.x, acc[3][2]);
            acc[3][3] = fma2(a23.y, bv1.y, acc[3][3]);
        }
        __syncthreads();
    }

    const int col = tx << 3;
    const float4 fb0 = *reinterpret_cast<const float4*>(&fc_b[col]);
    const float4 fb1 = *reinterpret_cast<const float4*>(&fc_b[col + 4]);

#pragma unroll
    for (int i = 0; i < 4; ++i) {
        const int r = r0 + (ty << 2) + i;
        const int s = s0 + (r >> 11);
        const int b = r & (BATCH - 1);
        float* dst = out + (size_t)b * SEQ * OUTDIM + (size_t)(SEQ - 1 - s) * OUTDIM + col;
        const float2 p0 = unpack2(acc[i][0]);
        const float2 p1 = unpack2(acc[i][1]);
        const float2 p2 = unpack2(acc[i][2]);
        const float2 p3 = unpack2(acc[i][3]);
        float4 o0, o1;
        o0.x = p0.x + fb0.x; o0.y = p0.y + fb0.y; o0.z = p1.x + fb0.z; o0.w = p1.y + fb0.w;
        o1.x = p2.x + fb1.x; o1.y = p2.y + fb1.y; o1.z = p3.x + fb1.z; o1.w = p3.y + fb1.w;
        *reinterpret_cast<float4*>(dst)     = o0;
        *reinterpret_cast<float4*>(dst + 4) = o1;
    }
}

// ---------------- launch ----------------
// inputs: hidden, w_ih, w_hh, b_ih, b_hh, fc_w, fc_b, seq_len
extern "C" void kernel_launch(void* const* d_in, const int* in_sizes, int n_in,
                              void* d_out, int out_size)
{
    const float* hidden = (const float*)d_in[0];
    const float* w_ih   = (const float*)d_in[1];
    const float* w_hh   = (const float*)d_in[2];
    const float* b_ih   = (const float*)d_in[3];
    const float* b_hh   = (const float*)d_in[4];
    const float* fc_w   = (const float*)d_in[5];
    const float* fc_b   = (const float*)d_in[6];
    float* out = (float*)d_out;

    cudaFuncSetAttribute(step_kernel, cudaFuncAttributeMaxDynamicSharedMemorySize, DSMEM_BYTES);

    prep_w4<<<(4 * HID * HID) / NT, NT>>>(w_ih, w_hh, fc_w);
    prep_b4<<<(4 * HID) / NT, NT>>>(w_ih, b_ih, b_hh, fc_b);
    conv_h0<<<(BATCH * HID) / NT, NT>>>(hidden);

    const dim3 gridS(BATCH / BM, (4 * HID) / BN);     // 16 x 16
    for (int s = 0; s < SEQ; ++s) {
        step_kernel<<<gridS, NT, DSMEM_BYTES>>>(s, hidden);
        if ((s & (RING - 1)) == RING - 1)
            fc_batch<<<RING * BATCH / FBM, NT>>>(s - RING + 1, fc_w, fc_b, out);
    }
}

// round 11
// speedup vs baseline: 2.9507x; 1.2223x over previous
#include <cuda_runtime.h>
#include <cuda_bf16.h>
#include <math.h>
#include <stdint.h>

// ---------------- problem constants ----------------
#define BATCH  2048
#define HID    512
#define INDIM  128
#define OUTDIM 128
#define SEQ    128
#define RING   16
#define NT     256

// ---------------- shared tiling (mma.sync bf16) ----------------
#define BM 128
#define BN 128              // step: 32 hcols x 4 gates; fc: 128 out cols
#define BKE 32              // K elements per iter
#define NCK (HID / BKE)     // 16
#define ROWB 80             // padded smem row bytes -> conflict-free ldmatrix
#define ARR_BYTES (128 * ROWB)      // 10240 per array
#define STG_BYTES (4 * ARR_BYTES)   // AH AL BH BL = 40960 per stage
#define DSMEM_BYTES (2 * STG_BYTES) // 81920

typedef unsigned long long u64;

// ---------------- static device scratch ----------------
__device__ __nv_bfloat16  g_hbh[(size_t)RING * BATCH * HID];     // h bf16 hi, 16-slot ring
__device__ __nv_bfloat16  g_hbl[(size_t)RING * BATCH * HID];     // h bf16 lo
__device__ __nv_bfloat16  g_W4h[(size_t)4 * HID * HID];          // combined W hi (rows n=4h+g)
__device__ __nv_bfloat16  g_W4l[(size_t)4 * HID * HID];
__device__ __nv_bfloat16  g_W40h[(size_t)4 * HID * HID];         // step-0 variant (x=0)
__device__ __nv_bfloat16  g_W40l[(size_t)4 * HID * HID];
__device__ __nv_bfloat16  g_fcwh[(size_t)OUTDIM * HID];          // fc_w bf16 hi
__device__ __nv_bfloat16  g_fcwl[(size_t)OUTDIM * HID];          // fc_w bf16 lo
__device__ float          g_b4[4 * HID];
__device__ float          g_b40[4 * HID];

// ---------------- PTX helpers (baseline sm_80-era; valid on sm_100) ----------------
__device__ __forceinline__ uint32_t smem_u32(const void* p) {
    uint32_t a;
    asm("{ .reg .u64 t; cvta.to.shared.u64 t, %1; cvt.u32.u64 %0, t; }" : "=r"(a) : "l"(p));
    return a;
}
__device__ __forceinline__ void cp16(uint32_t dst, const void* src) {
    asm volatile("cp.async.cg.shared.global [%0], [%1], 16;" :: "r"(dst), "l"(src));
}
__device__ __forceinline__ void cp_commit() {
    asm volatile("cp.async.commit_group;" ::: "memory");
}
__device__ __forceinline__ void cp_wait1() {
    asm volatile("cp.async.wait_group 1;" ::: "memory");
}
__device__ __forceinline__ void cp_wait0() {
    asm volatile("cp.async.wait_group 0;" ::: "memory");
}
__device__ __forceinline__ void ldm_x4(uint32_t* r, uint32_t addr) {
    asm volatile("ldmatrix.sync.aligned.m8n8.x4.shared.b16 {%0,%1,%2,%3}, [%4];"
        : "=r"(r[0]), "=r"(r[1]), "=r"(r[2]), "=r"(r[3]) : "r"(addr));
}
__device__ __forceinline__ void mma_bf16(float* d, const uint32_t* a, const uint32_t* b) {
    asm volatile("mma.sync.aligned.m16n8k16.row.col.f32.bf16.bf16.f32 "
        "{%0,%1,%2,%3}, {%4,%5,%6,%7}, {%8,%9}, {%0,%1,%2,%3};"
        : "+f"(d[0]), "+f"(d[1]), "+f"(d[2]), "+f"(d[3])
        : "r"(a[0]), "r"(a[1]), "r"(a[2]), "r"(a[3]), "r"(b[0]), "r"(b[1]));
}

// ---------------- MUFU-free activations ----------------
__device__ __forceinline__ float fexp(float x) {
    x = fminf(fmaxf(x, -30.0f), 30.0f);
    float y = x * 1.4426950408889634f;
    float m = y + 12582912.0f;
    int   n = __float_as_int(m) - 0x4B400000;
    float f = y - (m - 12582912.0f);
    float p =              1.5403530e-4f;
    p = fmaf(p, f, 1.3333558e-3f);
    p = fmaf(p, f, 9.6181291e-3f);
    p = fmaf(p, f, 5.5504109e-2f);
    p = fmaf(p, f, 2.4022651e-1f);
    p = fmaf(p, f, 6.9314718e-1f);
    p = fmaf(p, f, 1.0f);
    return __int_as_float(__float_as_int(p) + (n << 23));
}
__device__ __forceinline__ float frcp(float d) {
    float x = __int_as_float(0x7EF311C3 - __float_as_int(d));
    x = x * fmaf(-d, x, 2.0f);
    x = x * fmaf(-d, x, 2.0f);
    x = x * fmaf(-d, x, 2.0f);
    return x;
}
__device__ __forceinline__ float fsig(float x)   { return frcp(1.0f + fexp(-x)); }
__device__ __forceinline__ float ftanh_(float y) { return fmaf(2.0f, fsig(2.0f * y), -1.0f); }
__device__ __forceinline__ float gru_comb(float pr, float pz, float pi, float ph, float hp) {
    float r  = fsig(pr);
    float z  = fsig(pz);
    float nn = ftanh_(fmaf(r, ph, pi));
    return fmaf(z, hp - nn, nn);
}

// ---------------- prep kernels ----------------
// Row n = hcol*4 + gate (0=R, 1=Z, 2=IN, 3=HN).
__global__ __launch_bounds__(NT)
void prep_w4(const float* __restrict__ w_ih, const float* __restrict__ w_hh,
             const float* __restrict__ fc_w)
{
    const int idx  = blockIdx.x * NT + threadIdx.x;
    const int k    = idx & (HID - 1);
    const int n    = idx >> 9;
    const int hcol = n >> 2;
    const int gate = n & 3;

    float acc = 0.0f;
    if (gate < 3) {
        const int wrow = gate * HID + hcol;
#pragma unroll 8
        for (int o = 0; o < INDIM; ++o)
            acc += w_ih[wrow * INDIM + o] * fc_w[o * HID + k];
    }
    float w4, w40;
    if (gate == 0)      { float w = w_hh[hcol * HID + k];             w4 = acc + w; w40 = w; }
    else if (gate == 1) { float w = w_hh[(HID + hcol) * HID + k];     w4 = acc + w; w40 = w; }
    else if (gate == 2) { w4 = acc; w40 = 0.0f; }
    else                { float w = w_hh[(2 * HID + hcol) * HID + k]; w4 = w;       w40 = w; }

    __nv_bfloat16 h1 = __float2bfloat16_rn(w4);
    g_W4h[idx]  = h1;
    g_W4l[idx]  = __float2bfloat16_rn(w4 - __bfloat162float(h1));
    __nv_bfloat16 h0 = __float2bfloat16_rn(w40);
    g_W40h[idx] = h0;
    g_W40l[idx] = __float2bfloat16_rn(w40 - __bfloat162float(h0));
}

__global__ __launch_bounds__(NT)
void prep_b4(const float* __restrict__ w_ih, const float* __restrict__ b_ih,
             const float* __restrict__ b_hh, const float* __restrict__ fc_b)
{
    const int n    = blockIdx.x * NT + threadIdx.x;
    const int hcol = n >> 2;
    const int gate = n & 3;

    float acc = 0.0f;
    if (gate < 3) {
        const int wrow = gate * HID + hcol;
#pragma unroll 8
        for (int o = 0; o < INDIM; ++o)
            acc += w_ih[wrow * INDIM + o] * fc_b[o];
    }
    float b, b0;
    if (gate == 0)      { b0 = b_ih[hcol] + b_hh[hcol];                 b = acc + b0; }
    else if (gate == 1) { b0 = b_ih[HID + hcol] + b_hh[HID + hcol];     b = acc + b0; }
    else if (gate == 2) { b0 = b_ih[2 * HID + hcol];                    b = acc + b0; }
    else                { b0 = b_hh[2 * HID + hcol];                    b = b0; }
    g_b4[n]  = b;
    g_b40[n] = b0;
}

// fc_w bf16 hi/lo split (for the HMMA fc kernel)
__global__ __launch_bounds__(NT)
void prep_fcw(const float* __restrict__ fc_w)
{
    const int i = blockIdx.x * NT + threadIdx.x;   // 0 .. 65535
    const float v = fc_w[i];
    __nv_bfloat16 h16 = __float2bfloat16_rn(v);
    g_fcwh[i] = h16;
    g_fcwl[i] = __float2bfloat16_rn(v - __bfloat162float(h16));
}

// Initial hidden -> bf16 hi/lo into ring slot 15 (read by step 0 as (0-1)&15).
__global__ __launch_bounds__(NT)
void conv_h0(const float* __restrict__ hsrc)
{
    const int i = blockIdx.x * NT + threadIdx.x;
    const float v = hsrc[i];
    __nv_bfloat16 h16 = __float2bfloat16_rn(v);
    g_hbh[(size_t)15 * BATCH * HID + i] = h16;
    g_hbl[(size_t)15 * BATCH * HID + i] = __float2bfloat16_rn(v - __bfloat162float(h16));
}

// ---------------- shared cp.async stage loader ----------------
extern __shared__ char dsm[];

__device__ __forceinline__ void issue_stage(
    uint32_t sb, const __nv_bfloat16* Abh, const __nv_bfloat16* Abl,
    const __nv_bfloat16* Bh_, const __nv_bfloat16* Bl_, int m0, int n0, int ck, int t)
{
    const size_t kof = (size_t)ck * BKE;
#pragma unroll
    for (int rep = 0; rep < 2; ++rep) {
        const int cid = t + (rep << 8);
        const int r = cid >> 2;
        const int c = cid & 3;
        const uint32_t dof = (uint32_t)r * ROWB + c * 16;
        const size_t sof = kof + c * 8;
        cp16(sb + dof,                 Abh + (size_t)(m0 + r) * HID + sof);
        cp16(sb + ARR_BYTES + dof,     Abl + (size_t)(m0 + r) * HID + sof);
        cp16(sb + 2 * ARR_BYTES + dof, Bh_ + (size_t)(n0 + r) * HID + sof);
        cp16(sb + 3 * ARR_BYTES + dof, Bl_ + (size_t)(n0 + r) * HID + sof);
    }
}

// Shared 3-pass HMMA mainloop over K=512 (acc[2][8][4] in caller regs).
#define HMMA_MAINLOOP(Abh, Abl, Bh_, Bl_, m0v, n0v)                                   \
    issue_stage(sb0, Abh, Abl, Bh_, Bl_, m0v, n0v, 0, t);                             \
    cp_commit();                                                                      \
    for (int ck = 0; ck < NCK; ++ck) {                                                \
        if (ck < NCK - 1) {                                                           \
            issue_stage(sb0 + ((ck + 1) & 1) * STG_BYTES, Abh, Abl, Bh_, Bl_,         \
                        m0v, n0v, ck + 1, t);                                         \
            cp_commit();                                                              \
            cp_wait1();                                                               \
        } else {                                                                      \
            cp_wait0();                                                               \
        }                                                                             \
        __syncthreads();                                                              \
        const uint32_t sbs = sb0 + (ck & 1) * STG_BYTES;                              \
        _Pragma("unroll")                                                             \
        for (int ks = 0; ks < 2; ++ks) {                                              \
            const uint32_t aA = sbs + (uint32_t)(warp_m * 32 + (lane & 15)) * ROWB    \
                              + (uint32_t)(ks * 2 + (lane >> 4)) * 16;                \
            uint32_t Ahf[2][4], Alf[2][4];                                            \
            ldm_x4(Ahf[0], aA);                                                       \
            ldm_x4(Ahf[1], aA + 16 * ROWB);                                           \
            ldm_x4(Alf[0], aA + ARR_BYTES);                                           \
            ldm_x4(Alf[1], aA + ARR_BYTES + 16 * ROWB);                               \
            _Pragma("unroll")                                                         \
            for (int p = 0; p < 4; ++p) {                                             \
                const uint32_t rB = (uint32_t)(warp_n * 64 + p * 16 + (lane & 7)      \
                                  + ((lane >> 4) & 1) * 8);                           \
                const uint32_t aB = sbs + 2 * ARR_BYTES + rB * ROWB                   \
                                  + (uint32_t)(ks * 2 + ((lane >> 3) & 1)) * 16;      \
                uint32_t Bhf[4], Blf[4];                                              \
                ldm_x4(Bhf, aB);                                                      \
                ldm_x4(Blf, aB + ARR_BYTES);                                          \
                _Pragma("unroll")                                                     \
                for (int mt = 0; mt < 2; ++mt) {                                      \
                    _Pragma("unroll")                                                 \
                    for (int hf = 0; hf < 2; ++hf) {                                  \
                        float* d = acc[mt][p * 2 + hf];                               \
                        mma_bf16(d, Ahf[mt], Bhf + hf * 2);                           \
                        mma_bf16(d, Ahf[mt], Blf + hf * 2);                           \
                        mma_bf16(d, Alf[mt], Bhf + hf * 2);                           \
                    }                                                                 \
                }                                                                     \
            }                                                                         \
        }                                                                             \
        __syncthreads();                                                              \
    }

// ---------------- mma.sync GRU step ----------------
// grid (16,16), 256 threads (8 warps, 4x2). C[128,128] = Ah*Bh + Ah*Bl + Al*Bh over K=512.
__global__ __launch_bounds__(NT, 2)
void step_kernel(int s)
{
    const uint32_t sb0 = smem_u32(dsm);

    const int t      = threadIdx.x;
    const int lane   = t & 31;
    const int wid    = t >> 5;
    const int warp_m = wid & 3;
    const int warp_n = wid >> 2;
    const int m0     = blockIdx.x * BM;
    const int n0     = blockIdx.y * BN;

    const size_t slot_p = (size_t)((s + RING - 1) & (RING - 1)) * BATCH * HID;
    const size_t slot_o = (size_t)(s & (RING - 1)) * BATCH * HID;
    const __nv_bfloat16* Abh = g_hbh + slot_p;
    const __nv_bfloat16* Abl = g_hbl + slot_p;
    const __nv_bfloat16* Wh  = s ? g_W4h : g_W40h;
    const __nv_bfloat16* Wl  = s ? g_W4l : g_W40l;
    const float* bias = s ? g_b4 : g_b40;
    __nv_bfloat16* hbh_o = g_hbh + slot_o;
    __nv_bfloat16* hbl_o = g_hbl + slot_o;

    float acc[2][8][4];
#pragma unroll
    for (int mt = 0; mt < 2; ++mt)
#pragma unroll
        for (int nt = 0; nt < 8; ++nt)
#pragma unroll
            for (int e = 0; e < 4; ++e) acc[mt][nt][e] = 0.0f;

    HMMA_MAINLOOP(Abh, Abl, Wh, Wl, m0, n0)

    // ---- epilogue: reunite gates via shfl, combine, stage, coalesced bf16 writeout ----
    float* stg = reinterpret_cast<float*>(dsm);   // 128 x 33 floats (reuses stage 0)
    const int lq  = lane >> 2;
    const int lr4 = lane & 3;
    const int hb  = n0 >> 2;

#pragma unroll
    for (int mt = 0; mt < 2; ++mt) {
#pragma unroll
        for (int nt = 0; nt < 8; ++nt) {
            float* a = acc[mt][nt];
            float sv0 = (lane & 1) ? a[0] : a[2];
            float rv0 = __shfl_xor_sync(0xffffffffu, sv0, 1);
            float sv1 = (lane & 1) ? a[1] : a[3];
            float rv1 = __shfl_xor_sync(0xffffffffu, sv1, 1);
            float gr, gz, gi, gh_;
            if (!(lane & 1)) { gr = a[0]; gz = a[1]; gi = rv0;  gh_ = rv1;  }
            else             { gr = rv0;  gz = rv1;  gi = a[2]; gh_ = a[3]; }
            const int rl = warp_m * 32 + mt * 16 + lq + ((lane & 1) << 3);
            const int c0 = n0 + warp_n * 64 + nt * 8 + lr4 * 2;
            const int hg = c0 >> 2;
            const float4 bb = *reinterpret_cast<const float4*>(&bias[hg << 2]);
            const size_t po = (size_t)(m0 + rl) * HID + hg;
            const float hp = __bfloat162float(Abh[po]) + __bfloat162float(Abl[po]);
            stg[rl * 33 + (hg - hb)] =
                gru_comb(gr + bb.x, gz + bb.y, gi + bb.z, gh_ + bb.w, hp);
        }
    }
    __syncthreads();

    {
        const int row  = t >> 1;
        const int half = t & 1;
        float v[16];
#pragma unroll
        for (int i = 0; i < 16; ++i) v[i] = stg[row * 33 + half * 16 + i];
        const size_t ro = (size_t)(m0 + row) * HID + hb + half * 16;
        uint32_t hw[8], lw[8];
#pragma unroll
        for (int i = 0; i < 8; ++i) {
            __nv_bfloat16 a0 = __float2bfloat16_rn(v[2 * i]);
            __nv_bfloat16 a1 = __float2bfloat16_rn(v[2 * i + 1]);
            __nv_bfloat16 b0 = __float2bfloat16_rn(v[2 * i]     - __bfloat162float(a0));
            __nv_bfloat16 b1 = __float2bfloat16_rn(v[2 * i + 1] - __bfloat162float(a1));
            hw[i] = (uint32_t)__bfloat16_as_ushort(a0) | ((uint32_t)__bfloat16_as_ushort(a1) << 16);
            lw[i] = (uint32_t)__bfloat16_as_ushort(b0) | ((uint32_t)__bfloat16_as_ushort(b1) << 16);
        }
        *reinterpret_cast<uint4*>(hbh_o + ro)     = make_uint4(hw[0], hw[1], hw[2], hw[3]);
        *reinterpret_cast<uint4*>(hbh_o + ro + 8) = make_uint4(hw[4], hw[5], hw[6], hw[7]);
        *reinterpret_cast<uint4*>(hbl_o + ro)     = make_uint4(lw[0], lw[1], lw[2], lw[3]);
        *reinterpret_cast<uint4*>(hbl_o + ro + 8) = make_uint4(lw[4], lw[5], lw[6], lw[7]);
    }
}

// ---------------- HMMA batched FC over the full ring ----------------
// Ring slots 0..15 hold steps s0..s0+15 in order; ring rows r = slot*2048 + b.
// C[32768,128] = Hring @ fc_w^T (+fc_b), written to out[b][SEQ-1-(s0+slot)][:].
__global__ __launch_bounds__(NT, 2)
void fc_hmma(int s0, const float* __restrict__ fc_b, float* __restrict__ out)
{
    const uint32_t sb0 = smem_u32(dsm);

    const int t      = threadIdx.x;
    const int lane   = t & 31;
    const int wid    = t >> 5;
    const int warp_m = wid & 3;
    const int warp_n = wid >> 2;
    const int m0     = blockIdx.x * BM;
    const int n0     = 0;

    float acc[2][8][4];
#pragma unroll
    for (int mt = 0; mt < 2; ++mt)
#pragma unroll
        for (int nt = 0; nt < 8; ++nt)
#pragma unroll
            for (int e = 0; e < 4; ++e) acc[mt][nt][e] = 0.0f;

    HMMA_MAINLOOP(g_hbh, g_hbl, g_fcwh, g_fcwl, m0, n0)

    // ---- epilogue: bias + direct write with seq reversal ----
    const int lq  = lane >> 2;
    const int lr4 = lane & 3;

#pragma unroll
    for (int mt = 0; mt < 2; ++mt) {
        const int rl0 = warp_m * 32 + mt * 16 + lq;
#pragma unroll
        for (int nt = 0; nt < 8; ++nt) {
            const int col = warp_n * 64 + nt * 8 + lr4 * 2;
            const float2 fb = *reinterpret_cast<const float2*>(&fc_b[col]);
            const float* a = acc[mt][nt];
#pragma unroll
            for (int half = 0; half < 2; ++half) {
                const int r    = m0 + rl0 + half * 8;
                const int slot = r >> 11;
                const int b    = r & (BATCH - 1);
                const int sAbs = s0 + slot;
                float2 o;
                o.x = a[half * 2 + 0] + fb.x;
                o.y = a[half * 2 + 1] + fb.y;
                *reinterpret_cast<float2*>(
                    out + (size_t)b * SEQ * OUTDIM + (size_t)(SEQ - 1 - sAbs) * OUTDIM + col) = o;
            }
        }
    }
}

// ---------------- launch ----------------
// inputs: hidden, w_ih, w_hh, b_ih, b_hh, fc_w, fc_b, seq_len
extern "C" void kernel_launch(void* const* d_in, const int* in_sizes, int n_in,
                              void* d_out, int out_size)
{
    const float* hidden = (const float*)d_in[0];
    const float* w_ih   = (const float*)d_in[1];
    const float* w_hh   = (const float*)d_in[2];
    const float* b_ih   = (const float*)d_in[3];
    const float* b_hh   = (const float*)d_in[4];
    const float* fc_w   = (const float*)d_in[5];
    const float* fc_b   = (const float*)d_in[6];
    float* out = (float*)d_out;

    cudaFuncSetAttribute(step_kernel, cudaFuncAttributeMaxDynamicSharedMemorySize, DSMEM_BYTES);
    cudaFuncSetAttribute(fc_hmma,    cudaFuncAttributeMaxDynamicSharedMemorySize, DSMEM_BYTES);

    prep_w4<<<(4 * HID * HID) / NT, NT>>>(w_ih, w_hh, fc_w);
    prep_b4<<<(4 * HID) / NT, NT>>>(w_ih, b_ih, b_hh, fc_b);
    prep_fcw<<<(OUTDIM * HID) / NT, NT>>>(fc_w);
    conv_h0<<<(BATCH * HID) / NT, NT>>>(hidden);

    const dim3 gridS(BATCH / BM, (4 * HID) / BN);     // 16 x 16
    for (int s = 0; s < SEQ; ++s) {
        step_kernel<<<gridS, NT, DSMEM_BYTES>>>(s);
        if ((s & (RING - 1)) == RING - 1)
            fc_hmma<<<RING * BATCH / BM, NT, DSMEM_BYTES>>>(s - RING + 1, fc_b, out);
    }
}